// round 1
// baseline (speedup 1.0000x reference)
#include <cuda_runtime.h>

#define FD 128          // feature dim
#define F4 32           // FD/4

static const int cNSOC = 100000;
static const int cNI2U = 50000;
static const int cESOC = 1600000;
static const int cEI2U = 800000;

// ---------------- scratch (device globals; no allocation allowed) ----------
__device__ float g_el1[cNI2U * FD];
__device__ float g_er1[cNI2U * FD];
__device__ float g_el2[cNSOC * FD];
__device__ float g_er2[cNSOC * FD];
__device__ float g_h1 [cNI2U * FD];   // layer-1 accumulation, then final h1
__device__ float g_s1 [cEI2U];
__device__ float g_s2 [cESOC];
__device__ float g_m1 [cNI2U];
__device__ float g_den1[cNI2U];
__device__ float g_m2 [cNSOC];
__device__ float g_den2[cNSOC];
__device__ int   g_map[cNSOC];        // -1, or index into g_h1 when mask true

__device__ __forceinline__ float lrelu(float x, float s) { return x > 0.f ? x : s * x; }

// ---------------- init: zero accumulators, -inf maxes, -1 map --------------
__global__ void k_init(float* __restrict__ out, int nout) {
    int i = blockIdx.x * blockDim.x + threadIdx.x;
    if (i < nout) out[i] = 0.f;
    if (i < cNI2U * FD) g_h1[i] = 0.f;
    if (i < cNSOC) {
        g_m2[i]  = __int_as_float(0xff800000);  // -inf
        g_den2[i] = 0.f;
        g_map[i] = -1;
    }
    if (i < cNI2U) {
        g_m1[i]  = __int_as_float(0xff800000);
        g_den1[i] = 0.f;
    }
}

// ---------------- GEMM: out[i] = feat(i) @ W + b ---------------------------
// LAYER==1: feat(i) = emb[nid[i]]          -> g_el1 / g_er1
// LAYER==2: feat(i) = map[i]>=0 ? h1[map[i]] : emb[i]   -> g_el2 / g_er2
// Block: 256 threads, 32 rows. smem: feat tile 16KB + W k-chunk 32KB = 48KB.
template<int LAYER, int WHICH>
__global__ void __launch_bounds__(256)
k_gemm(const float* __restrict__ emb, const int* __restrict__ nid,
       const float* __restrict__ W, const float* __restrict__ bias, int nrows)
{
    __shared__ float sf[32][FD];
    __shared__ float sw[64][FD];

    float* out;
    if (LAYER == 1) out = (WHICH == 0) ? g_el1 : g_er1;
    else            out = (WHICH == 0) ? g_el2 : g_er2;

    const int tid = threadIdx.x;
    const int rowbase = blockIdx.x * 32;

    // load feature tile (gathered)
    for (int s = tid; s < 32 * F4; s += 256) {
        int r = s >> 5, c4 = s & 31;
        int g = rowbase + r;
        float4 v = make_float4(0.f, 0.f, 0.f, 0.f);
        if (g < nrows) {
            const float* p;
            if (LAYER == 1) {
                p = emb + (size_t)nid[g] * FD;
            } else {
                int mj = g_map[g];
                p = (mj >= 0) ? (g_h1 + (size_t)mj * FD) : (emb + (size_t)g * FD);
            }
            v = ((const float4*)p)[c4];
        }
        ((float4*)&sf[r][0])[c4] = v;
    }

    const int warp = tid >> 5, lane = tid & 31;
    float acc[4][4];
#pragma unroll
    for (int r = 0; r < 4; r++)
#pragma unroll
        for (int c = 0; c < 4; c++) acc[r][c] = 0.f;

    for (int chunk = 0; chunk < 2; chunk++) {
        __syncthreads();
        for (int s = tid; s < 64 * F4; s += 256) {
            int k = s >> 5, c4 = s & 31;
            ((float4*)&sw[k][0])[c4] =
                ((const float4*)(W + (size_t)(chunk * 64 + k) * FD))[c4];
        }
        __syncthreads();
#pragma unroll 4
        for (int k = 0; k < 64; k++) {
            float4 wv = ((float4*)&sw[k][0])[lane];
            int ka = chunk * 64 + k;
#pragma unroll
            for (int r = 0; r < 4; r++) {
                float f = sf[warp * 4 + r][ka];
                acc[r][0] += f * wv.x;
                acc[r][1] += f * wv.y;
                acc[r][2] += f * wv.z;
                acc[r][3] += f * wv.w;
            }
        }
    }

    float4 bv = ((const float4*)bias)[lane];
#pragma unroll
    for (int r = 0; r < 4; r++) {
        int g = rowbase + warp * 4 + r;
        if (g < nrows) {
            float4 o = make_float4(acc[r][0] + bv.x, acc[r][1] + bv.y,
                                   acc[r][2] + bv.z, acc[r][3] + bv.w);
            ((float4*)(out + (size_t)g * FD))[lane] = o;
        }
    }
}

// ---------------- edge pass A: logits + segment max -------------------------
// warp per edge: s[e] = leaky_relu(el[src]+er[dst], .2) . attn ; atomicMax m[dst]
template<int LAYER>
__global__ void __launch_bounds__(256)
k_edge_a(const int* __restrict__ src, const int* __restrict__ dst,
         const float* __restrict__ attn, int E)
{
    const float* el = (LAYER == 1) ? g_el1 : g_el2;
    const float* er = (LAYER == 1) ? g_er1 : g_er2;
    float* s = (LAYER == 1) ? g_s1 : g_s2;
    float* m = (LAYER == 1) ? g_m1 : g_m2;

    int e = (blockIdx.x * blockDim.x + threadIdx.x) >> 5;
    int lane = threadIdx.x & 31;
    if (e >= E) return;
    int u = __ldg(src + e), v = __ldg(dst + e);

    float4 a = ((const float4*)(el + (size_t)u * FD))[lane];
    float4 b = ((const float4*)(er + (size_t)v * FD))[lane];
    float4 t = ((const float4*)attn)[lane];

    float x, sum = 0.f;
    x = a.x + b.x; sum += lrelu(x, 0.2f) * t.x;
    x = a.y + b.y; sum += lrelu(x, 0.2f) * t.y;
    x = a.z + b.z; sum += lrelu(x, 0.2f) * t.z;
    x = a.w + b.w; sum += lrelu(x, 0.2f) * t.w;
#pragma unroll
    for (int o = 16; o; o >>= 1) sum += __shfl_xor_sync(0xffffffffu, sum, o);

    if (lane == 0) {
        s[e] = sum;
        if (sum >= 0.f) atomicMax((int*)(m + v), __float_as_int(sum));
        else            atomicMin((unsigned int*)(m + v), __float_as_uint(sum));
    }
}

// ---------------- edge pass B: exp + segment sum ----------------------------
template<int LAYER>
__global__ void __launch_bounds__(256)
k_edge_b(const int* __restrict__ dst, int E)
{
    float* s = (LAYER == 1) ? g_s1 : g_s2;
    const float* m = (LAYER == 1) ? g_m1 : g_m2;
    float* den = (LAYER == 1) ? g_den1 : g_den2;

    int e = blockIdx.x * blockDim.x + threadIdx.x;
    if (e >= E) return;
    int v = __ldg(dst + e);
    float ex = expf(s[e] - m[v]);
    s[e] = ex;
    atomicAdd(den + v, ex);
}

// ---------------- edge pass C: weighted scatter-add --------------------------
// warp per edge: out[dst] += el[src] * (ex / den[dst])  via red.global.add.v4.f32
template<int LAYER>
__global__ void __launch_bounds__(256)
k_edge_c(const int* __restrict__ src, const int* __restrict__ dst,
         float* __restrict__ out2, int E)
{
    const float* el  = (LAYER == 1) ? g_el1  : g_el2;
    const float* s   = (LAYER == 1) ? g_s1   : g_s2;
    const float* den = (LAYER == 1) ? g_den1 : g_den2;
    float* out = (LAYER == 1) ? g_h1 : out2;

    int e = (blockIdx.x * blockDim.x + threadIdx.x) >> 5;
    int lane = threadIdx.x & 31;
    if (e >= E) return;
    int u = __ldg(src + e), v = __ldg(dst + e);
    float alpha = __ldg(s + e) / __ldg(den + v);

    float4 a = ((const float4*)(el + (size_t)u * FD))[lane];
    a.x *= alpha; a.y *= alpha; a.z *= alpha; a.w *= alpha;
    float* p = out + (size_t)v * FD + lane * 4;
    asm volatile("red.global.add.v4.f32 [%0], {%1,%2,%3,%4};"
                 :: "l"(p), "f"(a.x), "f"(a.y), "f"(a.z), "f"(a.w) : "memory");
}

// ---------------- finalize layer1: leaky, mask, build map -------------------
__global__ void __launch_bounds__(256)
k_fin1(const int* __restrict__ nid, int n1)
{
    int j = (blockIdx.x * blockDim.x + threadIdx.x) >> 5;
    int lane = threadIdx.x & 31;
    if (j >= n1) return;
    float4* p = ((float4*)g_h1) + (size_t)j * F4 + lane;
    float4 h = *p;
    h.x = lrelu(h.x, 0.01f); h.y = lrelu(h.y, 0.01f);
    h.z = lrelu(h.z, 0.01f); h.w = lrelu(h.w, 0.01f);
    *p = h;
    float sum = h.x + h.y + h.z + h.w;
#pragma unroll
    for (int o = 16; o; o >>= 1) sum += __shfl_xor_sync(0xffffffffu, sum, o);
    if (lane == 0 && sum != 0.f) g_map[nid[j]] = j;
}

// ---------------- finalize layer2: elementwise leaky on output --------------
__global__ void __launch_bounds__(256)
k_fin2(float* __restrict__ out, int n)
{
    int i = blockIdx.x * blockDim.x + threadIdx.x;
    if (i >= n) return;
    float x = out[i];
    out[i] = lrelu(x, 0.01f);
}

// ---------------- launch -----------------------------------------------------
extern "C" void kernel_launch(void* const* d_in, const int* in_sizes, int n_in,
                              void* d_out, int out_size)
{
    const float* emb     = (const float*)d_in[0];
    const int*   i2u_src = (const int*)d_in[1];
    const int*   i2u_dst = (const int*)d_in[2];
    const int*   i2u_nid = (const int*)d_in[3];
    const int*   soc_src = (const int*)d_in[4];
    const int*   soc_dst = (const int*)d_in[5];
    const float* Ws1 = (const float*)d_in[6];
    const float* bs1 = (const float*)d_in[7];
    const float* Wd1 = (const float*)d_in[8];
    const float* bd1 = (const float*)d_in[9];
    const float* at1 = (const float*)d_in[10];
    const float* Ws2 = (const float*)d_in[11];
    const float* bs2 = (const float*)d_in[12];
    const float* Wd2 = (const float*)d_in[13];
    const float* bd2 = (const float*)d_in[14];
    const float* at2 = (const float*)d_in[15];
    float* out = (float*)d_out;

    const int E1 = in_sizes[1];
    const int E2 = in_sizes[4];
    const int N1 = in_sizes[3];

    // 0) init everything (d_out is poisoned -> must zero; it is the L2 accumulator)
    k_init<<<(out_size + 255) / 256, 256>>>(out, out_size);

    // 1) layer-1 projections
    k_gemm<1, 0><<<(N1 + 31) / 32, 256>>>(emb, i2u_nid, Ws1, bs1, N1);
    k_gemm<1, 1><<<(N1 + 31) / 32, 256>>>(emb, i2u_nid, Wd1, bd1, N1);

    // 2) layer-1 edge softmax + aggregate (warp per edge -> E/8 blocks of 256)
    k_edge_a<1><<<(E1 + 7) / 8, 256>>>(i2u_src, i2u_dst, at1, E1);
    k_edge_b<1><<<(E1 + 255) / 256, 256>>>(i2u_dst, E1);
    k_edge_c<1><<<(E1 + 7) / 8, 256>>>(i2u_src, i2u_dst, out, E1);

    // 3) finalize h1, build scatter map
    k_fin1<<<(N1 + 7) / 8, 256>>>(i2u_nid, N1);

    // 4) layer-2 projections (feature = map>=0 ? h1 : embedding)
    const int NS = out_size / FD;
    k_gemm<2, 0><<<(NS + 31) / 32, 256>>>(emb, nullptr, Ws2, bs2, NS);
    k_gemm<2, 1><<<(NS + 31) / 32, 256>>>(emb, nullptr, Wd2, bd2, NS);

    // 5) layer-2 edge softmax + aggregate directly into d_out
    k_edge_a<2><<<(E2 + 7) / 8, 256>>>(soc_src, soc_dst, at2, E2);
    k_edge_b<2><<<(E2 + 255) / 256, 256>>>(soc_dst, E2);
    k_edge_c<2><<<(E2 + 7) / 8, 256>>>(soc_src, soc_dst, out, E2);

    // 6) module activation
    k_fin2<<<(out_size + 255) / 256, 256>>>(out, out_size);
}

// round 2
// speedup vs baseline: 1.3630x; 1.3630x over previous
#include <cuda_runtime.h>

#define FD 128          // feature dim
#define F4 32           // FD/4

static const int cNSOC = 100000;
static const int cNI2U = 50000;
static const int cESOC = 1600000;
static const int cEI2U = 800000;

// ---------------- scratch (device globals; no allocation allowed) ----------
__device__ float g_el1[cNI2U * FD];
__device__ float g_er1[cNI2U * FD];
__device__ float g_el2[cNSOC * FD];
__device__ float g_er2[cNSOC * FD];
__device__ float g_h1 [cNI2U * FD];   // layer-1 accumulation, then final h1
__device__ float g_s1 [cEI2U];
__device__ float g_s2 [cESOC];
__device__ float g_m1 [cNI2U];
__device__ float g_den1[cNI2U];
__device__ float g_m2 [cNSOC];
__device__ float g_den2[cNSOC];
__device__ int   g_map[cNSOC];        // -1, or index into g_h1 when mask true

__device__ __forceinline__ float lrelu(float x, float s) { return x > 0.f ? x : s * x; }

// ---------------- init: zero accumulators, -inf maxes, -1 map --------------
__global__ void k_init(float* __restrict__ out, int nout) {
    int i = blockIdx.x * blockDim.x + threadIdx.x;
    if (i < nout) out[i] = 0.f;
    if (i < cNI2U * FD) g_h1[i] = 0.f;
    if (i < cNSOC) {
        g_m2[i]  = __int_as_float(0xff800000);  // -inf
        g_den2[i] = 0.f;
        g_map[i] = -1;
    }
    if (i < cNI2U) {
        g_m1[i]  = __int_as_float(0xff800000);
        g_den1[i] = 0.f;
    }
}

// ---------------- fused dual GEMM: el = feat@Ws+bs, er = feat@Wd+bd --------
// LAYER==1: feat(i) = emb[nid[i]]
// LAYER==2: feat(i) = map[i]>=0 ? h1[map[i]] : emb[i]
// 256 threads, 64 rows/block. smem: feat 32KB + 2 x W-chunk(16k) 16KB = 48KB.
// Inner product uses packed fma.rn.f32x2 (FFMA2) -> 2x fp32 FMA throughput,
// bit-identical rounding to scalar FFMA.
template<int LAYER>
__global__ void __launch_bounds__(256)
k_gemm2(const float* __restrict__ emb, const int* __restrict__ nid,
        const float* __restrict__ Ws, const float* __restrict__ bs,
        const float* __restrict__ Wd, const float* __restrict__ bd, int nrows)
{
    __shared__ float sf [64][FD];   // 32 KB
    __shared__ float sws[16][FD];   // 8 KB
    __shared__ float swd[16][FD];   // 8 KB

    float* outS = (LAYER == 1) ? g_el1 : g_el2;
    float* outD = (LAYER == 1) ? g_er1 : g_er2;

    const int tid = threadIdx.x;
    const int rowbase = blockIdx.x * 64;

    // gather feature tile
    for (int s = tid; s < 64 * F4; s += 256) {
        int r = s >> 5, c4 = s & 31;
        int g = rowbase + r;
        float4 v = make_float4(0.f, 0.f, 0.f, 0.f);
        if (g < nrows) {
            const float* p;
            if (LAYER == 1) {
                p = emb + (size_t)__ldg(nid + g) * FD;
            } else {
                int mj = g_map[g];
                p = (mj >= 0) ? (g_h1 + (size_t)mj * FD) : (emb + (size_t)g * FD);
            }
            v = ((const float4*)p)[c4];
        }
        ((float4*)&sf[r][0])[c4] = v;
    }

    const int warp = tid >> 5, lane = tid & 31;
    ulonglong2 accS[8], accD[8];
#pragma unroll
    for (int r = 0; r < 8; r++) {
        accS[r].x = 0ull; accS[r].y = 0ull;
        accD[r].x = 0ull; accD[r].y = 0ull;
    }

    for (int ch = 0; ch < 8; ch++) {
        __syncthreads();
        for (int s = tid; s < 16 * F4; s += 256) {
            int k = s >> 5, c4 = s & 31;
            ((float4*)&sws[k][0])[c4] =
                ((const float4*)(Ws + (size_t)(ch * 16 + k) * FD))[c4];
            ((float4*)&swd[k][0])[c4] =
                ((const float4*)(Wd + (size_t)(ch * 16 + k) * FD))[c4];
        }
        __syncthreads();
#pragma unroll
        for (int k = 0; k < 16; k++) {
            ulonglong2 ws = ((const ulonglong2*)&sws[k][0])[lane];
            ulonglong2 wd = ((const ulonglong2*)&swd[k][0])[lane];
#pragma unroll
            for (int r = 0; r < 8; r++) {
                float f = sf[warp * 8 + r][ch * 16 + k];
                unsigned long long fp;
                asm("mov.b64 %0, {%1, %1};" : "=l"(fp) : "f"(f));
                asm("fma.rn.f32x2 %0, %1, %2, %0;" : "+l"(accS[r].x) : "l"(fp), "l"(ws.x));
                asm("fma.rn.f32x2 %0, %1, %2, %0;" : "+l"(accS[r].y) : "l"(fp), "l"(ws.y));
                asm("fma.rn.f32x2 %0, %1, %2, %0;" : "+l"(accD[r].x) : "l"(fp), "l"(wd.x));
                asm("fma.rn.f32x2 %0, %1, %2, %0;" : "+l"(accD[r].y) : "l"(fp), "l"(wd.y));
            }
        }
    }

    float4 bsv = ((const float4*)bs)[lane];
    float4 bdv = ((const float4*)bd)[lane];
#pragma unroll
    for (int r = 0; r < 8; r++) {
        int g = rowbase + warp * 8 + r;
        if (g < nrows) {
            float x0, x1, x2, x3;
            asm("mov.b64 {%0,%1}, %2;" : "=f"(x0), "=f"(x1) : "l"(accS[r].x));
            asm("mov.b64 {%0,%1}, %2;" : "=f"(x2), "=f"(x3) : "l"(accS[r].y));
            float4 o = make_float4(x0 + bsv.x, x1 + bsv.y, x2 + bsv.z, x3 + bsv.w);
            ((float4*)(outS + (size_t)g * FD))[lane] = o;
            asm("mov.b64 {%0,%1}, %2;" : "=f"(x0), "=f"(x1) : "l"(accD[r].x));
            asm("mov.b64 {%0,%1}, %2;" : "=f"(x2), "=f"(x3) : "l"(accD[r].y));
            float4 o2 = make_float4(x0 + bdv.x, x1 + bdv.y, x2 + bdv.z, x3 + bdv.w);
            ((float4*)(outD + (size_t)g * FD))[lane] = o2;
        }
    }
}

// ---------------- edge pass A: logits + segment max -------------------------
// 4 edges per warp, 8 lanes per edge. Lane (sub, sl) covers float4 slices
// sl + 8j (j=0..3) of the 128-float rows -> 12 independent LDG.128 per lane.
template<int LAYER>
__global__ void __launch_bounds__(256)
k_edge_a(const int* __restrict__ src, const int* __restrict__ dst,
         const float* __restrict__ attn, int E)
{
    const float* el = (LAYER == 1) ? g_el1 : g_el2;
    const float* er = (LAYER == 1) ? g_er1 : g_er2;
    float* s = (LAYER == 1) ? g_s1 : g_s2;
    float* m = (LAYER == 1) ? g_m1 : g_m2;

    int wg   = (blockIdx.x * blockDim.x + threadIdx.x) >> 5;
    int lane = threadIdx.x & 31;
    int sub  = lane >> 3;          // edge within warp (0..3)
    int sl   = lane & 7;           // slot within edge (0..7)
    int e = wg * 4 + sub;
    bool valid = e < E;
    int u = valid ? __ldg(src + e) : 0;
    int v = valid ? __ldg(dst + e) : 0;

    const float4* pa = (const float4*)(el + (size_t)u * FD);
    const float4* pb = (const float4*)(er + (size_t)v * FD);
    const float4* pt = (const float4*)attn;

    float4 a0 = pa[sl],      a1 = pa[sl + 8],  a2 = pa[sl + 16], a3 = pa[sl + 24];
    float4 b0 = pb[sl],      b1 = pb[sl + 8],  b2 = pb[sl + 16], b3 = pb[sl + 24];
    float4 t0 = pt[sl],      t1 = pt[sl + 8],  t2 = pt[sl + 16], t3 = pt[sl + 24];

    float sum = 0.f;
    sum += lrelu(a0.x + b0.x, 0.2f) * t0.x; sum += lrelu(a0.y + b0.y, 0.2f) * t0.y;
    sum += lrelu(a0.z + b0.z, 0.2f) * t0.z; sum += lrelu(a0.w + b0.w, 0.2f) * t0.w;
    sum += lrelu(a1.x + b1.x, 0.2f) * t1.x; sum += lrelu(a1.y + b1.y, 0.2f) * t1.y;
    sum += lrelu(a1.z + b1.z, 0.2f) * t1.z; sum += lrelu(a1.w + b1.w, 0.2f) * t1.w;
    sum += lrelu(a2.x + b2.x, 0.2f) * t2.x; sum += lrelu(a2.y + b2.y, 0.2f) * t2.y;
    sum += lrelu(a2.z + b2.z, 0.2f) * t2.z; sum += lrelu(a2.w + b2.w, 0.2f) * t2.w;
    sum += lrelu(a3.x + b3.x, 0.2f) * t3.x; sum += lrelu(a3.y + b3.y, 0.2f) * t3.y;
    sum += lrelu(a3.z + b3.z, 0.2f) * t3.z; sum += lrelu(a3.w + b3.w, 0.2f) * t3.w;

#pragma unroll
    for (int o = 4; o; o >>= 1) sum += __shfl_xor_sync(0xffffffffu, sum, o);

    if (sl == 0 && valid) {
        s[e] = sum;
        if (sum >= 0.f) atomicMax((int*)(m + v), __float_as_int(sum));
        else            atomicMin((unsigned int*)(m + v), __float_as_uint(sum));
    }
}

// ---------------- edge pass B: exp + segment sum ----------------------------
template<int LAYER>
__global__ void __launch_bounds__(256)
k_edge_b(const int* __restrict__ dst, int E)
{
    float* s = (LAYER == 1) ? g_s1 : g_s2;
    const float* m = (LAYER == 1) ? g_m1 : g_m2;
    float* den = (LAYER == 1) ? g_den1 : g_den2;

    int e = blockIdx.x * blockDim.x + threadIdx.x;
    if (e >= E) return;
    int v = __ldg(dst + e);
    float ex = expf(s[e] - m[v]);
    s[e] = ex;
    atomicAdd(den + v, ex);
}

// ---------------- edge pass C: weighted scatter-add --------------------------
// 4 edges per warp, 8 lanes per edge, red.global.add.v4.f32 accumulation.
template<int LAYER>
__global__ void __launch_bounds__(256)
k_edge_c(const int* __restrict__ src, const int* __restrict__ dst,
         float* __restrict__ out2, int E)
{
    const float* el  = (LAYER == 1) ? g_el1  : g_el2;
    const float* s   = (LAYER == 1) ? g_s1   : g_s2;
    const float* den = (LAYER == 1) ? g_den1 : g_den2;
    float* out = (LAYER == 1) ? g_h1 : out2;

    int wg   = (blockIdx.x * blockDim.x + threadIdx.x) >> 5;
    int lane = threadIdx.x & 31;
    int sub  = lane >> 3;
    int sl   = lane & 7;
    int e = wg * 4 + sub;
    bool valid = e < E;
    int u = valid ? __ldg(src + e) : 0;
    int v = valid ? __ldg(dst + e) : 0;

    float alpha = valid ? (__ldg(s + e) / __ldg(den + v)) : 0.f;

    const float4* pa = (const float4*)(el + (size_t)u * FD);
    float4 a0 = pa[sl], a1 = pa[sl + 8], a2 = pa[sl + 16], a3 = pa[sl + 24];

    a0.x *= alpha; a0.y *= alpha; a0.z *= alpha; a0.w *= alpha;
    a1.x *= alpha; a1.y *= alpha; a1.z *= alpha; a1.w *= alpha;
    a2.x *= alpha; a2.y *= alpha; a2.z *= alpha; a2.w *= alpha;
    a3.x *= alpha; a3.y *= alpha; a3.z *= alpha; a3.w *= alpha;

    if (valid) {
        float* base = out + (size_t)v * FD + sl * 4;
        asm volatile("red.global.add.v4.f32 [%0], {%1,%2,%3,%4};"
                     :: "l"(base),       "f"(a0.x), "f"(a0.y), "f"(a0.z), "f"(a0.w) : "memory");
        asm volatile("red.global.add.v4.f32 [%0], {%1,%2,%3,%4};"
                     :: "l"(base + 32),  "f"(a1.x), "f"(a1.y), "f"(a1.z), "f"(a1.w) : "memory");
        asm volatile("red.global.add.v4.f32 [%0], {%1,%2,%3,%4};"
                     :: "l"(base + 64),  "f"(a2.x), "f"(a2.y), "f"(a2.z), "f"(a2.w) : "memory");
        asm volatile("red.global.add.v4.f32 [%0], {%1,%2,%3,%4};"
                     :: "l"(base + 96),  "f"(a3.x), "f"(a3.y), "f"(a3.z), "f"(a3.w) : "memory");
    }
}

// ---------------- finalize layer1: leaky, mask, build map -------------------
__global__ void __launch_bounds__(256)
k_fin1(const int* __restrict__ nid, int n1)
{
    int j = (blockIdx.x * blockDim.x + threadIdx.x) >> 5;
    int lane = threadIdx.x & 31;
    if (j >= n1) return;
    float4* p = ((float4*)g_h1) + (size_t)j * F4 + lane;
    float4 h = *p;
    h.x = lrelu(h.x, 0.01f); h.y = lrelu(h.y, 0.01f);
    h.z = lrelu(h.z, 0.01f); h.w = lrelu(h.w, 0.01f);
    *p = h;
    float sum = h.x + h.y + h.z + h.w;
#pragma unroll
    for (int o = 16; o; o >>= 1) sum += __shfl_xor_sync(0xffffffffu, sum, o);
    if (lane == 0 && sum != 0.f) g_map[nid[j]] = j;
}

// ---------------- finalize layer2: elementwise leaky on output --------------
__global__ void __launch_bounds__(256)
k_fin2(float* __restrict__ out, int n)
{
    int i = blockIdx.x * blockDim.x + threadIdx.x;
    if (i >= n) return;
    float x = out[i];
    out[i] = lrelu(x, 0.01f);
}

// ---------------- launch -----------------------------------------------------
extern "C" void kernel_launch(void* const* d_in, const int* in_sizes, int n_in,
                              void* d_out, int out_size)
{
    const float* emb     = (const float*)d_in[0];
    const int*   i2u_src = (const int*)d_in[1];
    const int*   i2u_dst = (const int*)d_in[2];
    const int*   i2u_nid = (const int*)d_in[3];
    const int*   soc_src = (const int*)d_in[4];
    const int*   soc_dst = (const int*)d_in[5];
    const float* Ws1 = (const float*)d_in[6];
    const float* bs1 = (const float*)d_in[7];
    const float* Wd1 = (const float*)d_in[8];
    const float* bd1 = (const float*)d_in[9];
    const float* at1 = (const float*)d_in[10];
    const float* Ws2 = (const float*)d_in[11];
    const float* bs2 = (const float*)d_in[12];
    const float* Wd2 = (const float*)d_in[13];
    const float* bd2 = (const float*)d_in[14];
    const float* at2 = (const float*)d_in[15];
    float* out = (float*)d_out;

    const int E1 = in_sizes[1];
    const int E2 = in_sizes[4];
    const int N1 = in_sizes[3];

    // 0) init (d_out is poisoned -> zero it; it is the layer-2 accumulator)
    k_init<<<(out_size + 255) / 256, 256>>>(out, out_size);

    // 1) layer-1 projections (fused el+er)
    k_gemm2<1><<<(N1 + 63) / 64, 256>>>(emb, i2u_nid, Ws1, bs1, Wd1, bd1, N1);

    // 2) layer-1 edge softmax + aggregate (32 edges per 256-thread block)
    k_edge_a<1><<<(E1 + 31) / 32, 256>>>(i2u_src, i2u_dst, at1, E1);
    k_edge_b<1><<<(E1 + 255) / 256, 256>>>(i2u_dst, E1);
    k_edge_c<1><<<(E1 + 31) / 32, 256>>>(i2u_src, i2u_dst, out, E1);

    // 3) finalize h1, build scatter map
    k_fin1<<<(N1 + 7) / 8, 256>>>(i2u_nid, N1);

    // 4) layer-2 projections (feature = map>=0 ? h1 : embedding)
    const int NS = out_size / FD;
    k_gemm2<2><<<(NS + 63) / 64, 256>>>(emb, nullptr, Ws2, bs2, Wd2, bd2, NS);

    // 5) layer-2 edge softmax + aggregate directly into d_out
    k_edge_a<2><<<(E2 + 31) / 32, 256>>>(soc_src, soc_dst, at2, E2);
    k_edge_b<2><<<(E2 + 255) / 256, 256>>>(soc_dst, E2);
    k_edge_c<2><<<(E2 + 31) / 32, 256>>>(soc_src, soc_dst, out, E2);

    // 6) module activation
    k_fin2<<<(out_size + 255) / 256, 256>>>(out, out_size);
}

// round 3
// speedup vs baseline: 2.0726x; 1.5206x over previous
#include <cuda_runtime.h>

#define FD 128          // feature dim
#define F4 32           // FD/4

static const int cNSOC = 100000;
static const int cNI2U = 50000;
static const int cESOC = 1600000;
static const int cEI2U = 800000;

// ---------------- scratch (device globals; no allocation allowed) ----------
__device__ __align__(16) float g_el1[cNI2U * FD];
__device__ __align__(16) float g_er1[cNI2U * FD];
__device__ __align__(16) float g_el2[cNSOC * FD];
__device__ __align__(16) float g_er2[cNSOC * FD];
__device__ __align__(16) float g_h1 [cNI2U * FD];
__device__ int   g_map [cNSOC];        // -1, or row index into g_h1
// CSR-by-destination structures
__device__ int   g_cnt1[cNI2U];        // counts, then reused as scatter cursor
__device__ int   g_cnt2[cNSOC];
__device__ int   g_off1[cNI2U + 1];
__device__ int   g_off2[cNSOC + 1];
__device__ int   g_csr1[cEI2U];        // src node id, grouped by dst
__device__ int   g_csr2[cESOC];
__device__ int   g_csum1[64];
__device__ int   g_csum2[128];

__device__ __forceinline__ float lrelu(float x, float s) { return x > 0.f ? x : s * x; }

// ---------------- init ------------------------------------------------------
__global__ void k_init() {
    int i = blockIdx.x * blockDim.x + threadIdx.x;
    if (i < cNSOC) { g_map[i] = -1; g_cnt2[i] = 0; }
    if (i < cNI2U) g_cnt1[i] = 0;
    if (i == 0) { g_off1[0] = 0; g_off2[0] = 0; }
}

// ---------------- CSR build: histogram --------------------------------------
__global__ void k_hist(const int* __restrict__ dst, int* __restrict__ cnt, int E) {
    int e = blockIdx.x * blockDim.x + threadIdx.x;
    if (e < E) atomicAdd(cnt + __ldg(dst + e), 1);
}

// ---------------- CSR build: 3-phase scan ------------------------------------
// A: per-1024 chunk inclusive scan -> off[i+1], chunk sums
__global__ void k_scanA(const int* __restrict__ cnt, int* __restrict__ off,
                        int* __restrict__ csum, int N) {
    __shared__ int sh[1024];
    int t = threadIdx.x;
    int i = blockIdx.x * 1024 + t;
    sh[t] = (i < N) ? cnt[i] : 0;
    __syncthreads();
#pragma unroll
    for (int d = 1; d < 1024; d <<= 1) {
        int add = (t >= d) ? sh[t - d] : 0;
        __syncthreads();
        sh[t] += add;
        __syncthreads();
    }
    if (i < N) off[i + 1] = sh[t];
    if (t == 1023) csum[blockIdx.x] = sh[t];
}
// B: single-block inclusive scan of chunk sums (n <= 128)
__global__ void k_scanB(int* __restrict__ csum, int n) {
    __shared__ int sh[128];
    int t = threadIdx.x;
    sh[t] = (t < n) ? csum[t] : 0;
    __syncthreads();
#pragma unroll
    for (int d = 1; d < 128; d <<= 1) {
        int add = (t >= d) ? sh[t - d] : 0;
        __syncthreads();
        sh[t] += add;
        __syncthreads();
    }
    if (t < n) csum[t] = sh[t];
}
// C: add chunk bases
__global__ void k_scanC(int* __restrict__ off, const int* __restrict__ csum, int N) {
    int i = blockIdx.x * blockDim.x + threadIdx.x;
    if (i >= N) return;
    int ch = i >> 10;
    if (ch > 0) off[i + 1] += csum[ch - 1];
}
// cursor = final offsets (reuse cnt array)
__global__ void k_cursor(int* __restrict__ cur, const int* __restrict__ off, int N) {
    int i = blockIdx.x * blockDim.x + threadIdx.x;
    if (i < N) cur[i] = off[i];
}
// scatter src ids into CSR slots
__global__ void k_scatter(const int* __restrict__ src, const int* __restrict__ dst,
                          int* __restrict__ cur, int* __restrict__ csr, int E) {
    int e = blockIdx.x * blockDim.x + threadIdx.x;
    if (e >= E) return;
    int pos = atomicAdd(cur + __ldg(dst + e), 1);
    csr[pos] = __ldg(src + e);
}

// ---------------- fused dual GEMM: el = feat@Ws+bs, er = feat@Wd+bd ---------
template<int LAYER>
__global__ void __launch_bounds__(256)
k_gemm2(const float* __restrict__ emb, const int* __restrict__ nid,
        const float* __restrict__ Ws, const float* __restrict__ bs,
        const float* __restrict__ Wd, const float* __restrict__ bd, int nrows)
{
    __shared__ float sf [64][FD];
    __shared__ float sws[16][FD];
    __shared__ float swd[16][FD];

    float* outS = (LAYER == 1) ? g_el1 : g_el2;
    float* outD = (LAYER == 1) ? g_er1 : g_er2;

    const int tid = threadIdx.x;
    const int rowbase = blockIdx.x * 64;

    for (int s = tid; s < 64 * F4; s += 256) {
        int r = s >> 5, c4 = s & 31;
        int g = rowbase + r;
        float4 v = make_float4(0.f, 0.f, 0.f, 0.f);
        if (g < nrows) {
            const float* p;
            if (LAYER == 1) {
                p = emb + (size_t)__ldg(nid + g) * FD;
            } else {
                int mj = g_map[g];
                p = (mj >= 0) ? (g_h1 + (size_t)mj * FD) : (emb + (size_t)g * FD);
            }
            v = ((const float4*)p)[c4];
        }
        ((float4*)&sf[r][0])[c4] = v;
    }

    const int warp = tid >> 5, lane = tid & 31;
    ulonglong2 accS[8], accD[8];
#pragma unroll
    for (int r = 0; r < 8; r++) {
        accS[r].x = 0ull; accS[r].y = 0ull;
        accD[r].x = 0ull; accD[r].y = 0ull;
    }

    for (int ch = 0; ch < 8; ch++) {
        __syncthreads();
        for (int s = tid; s < 16 * F4; s += 256) {
            int k = s >> 5, c4 = s & 31;
            ((float4*)&sws[k][0])[c4] =
                ((const float4*)(Ws + (size_t)(ch * 16 + k) * FD))[c4];
            ((float4*)&swd[k][0])[c4] =
                ((const float4*)(Wd + (size_t)(ch * 16 + k) * FD))[c4];
        }
        __syncthreads();
#pragma unroll
        for (int k = 0; k < 16; k++) {
            ulonglong2 ws = ((const ulonglong2*)&sws[k][0])[lane];
            ulonglong2 wd = ((const ulonglong2*)&swd[k][0])[lane];
#pragma unroll
            for (int r = 0; r < 8; r++) {
                float f = sf[warp * 8 + r][ch * 16 + k];
                unsigned long long fp;
                asm("mov.b64 %0, {%1, %1};" : "=l"(fp) : "f"(f));
                asm("fma.rn.f32x2 %0, %1, %2, %0;" : "+l"(accS[r].x) : "l"(fp), "l"(ws.x));
                asm("fma.rn.f32x2 %0, %1, %2, %0;" : "+l"(accS[r].y) : "l"(fp), "l"(ws.y));
                asm("fma.rn.f32x2 %0, %1, %2, %0;" : "+l"(accD[r].x) : "l"(fp), "l"(wd.x));
                asm("fma.rn.f32x2 %0, %1, %2, %0;" : "+l"(accD[r].y) : "l"(fp), "l"(wd.y));
            }
        }
    }

    float4 bsv = ((const float4*)bs)[lane];
    float4 bdv = ((const float4*)bd)[lane];
#pragma unroll
    for (int r = 0; r < 8; r++) {
        int g = rowbase + warp * 8 + r;
        if (g < nrows) {
            float x0, x1, x2, x3;
            asm("mov.b64 {%0,%1}, %2;" : "=f"(x0), "=f"(x1) : "l"(accS[r].x));
            asm("mov.b64 {%0,%1}, %2;" : "=f"(x2), "=f"(x3) : "l"(accS[r].y));
            ((float4*)(outS + (size_t)g * FD))[lane] =
                make_float4(x0 + bsv.x, x1 + bsv.y, x2 + bsv.z, x3 + bsv.w);
            asm("mov.b64 {%0,%1}, %2;" : "=f"(x0), "=f"(x1) : "l"(accD[r].x));
            asm("mov.b64 {%0,%1}, %2;" : "=f"(x2), "=f"(x3) : "l"(accD[r].y));
            ((float4*)(outD + (size_t)g * FD))[lane] =
                make_float4(x0 + bdv.x, x1 + bdv.y, x2 + bdv.z, x3 + bdv.w);
        }
    }
}

// ---------------- fused per-node GATv2 aggregation ---------------------------
// One warp per dst node. Whole 128-dim row lives as float4 per lane.
// Single pass over incident edges: gather el[src], logit, exp, accumulate.
// LAYER==1: writes h1 (+leaky 0.01) and g_map.  LAYER==2: writes d_out (+leaky).
template<int LAYER>
__global__ void __launch_bounds__(256)
k_node(const float* __restrict__ attn, float* __restrict__ out,
       const int* __restrict__ nid, int N)
{
    const float* el  = (LAYER == 1) ? g_el1  : g_el2;
    const float* er  = (LAYER == 1) ? g_er1  : g_er2;
    const int*   off = (LAYER == 1) ? g_off1 : g_off2;
    const int*   csr = (LAYER == 1) ? g_csr1 : g_csr2;

    int v    = (blockIdx.x * blockDim.x + threadIdx.x) >> 5;
    int lane = threadIdx.x & 31;
    if (v >= N) return;

    int i0 = __ldg(off + v), i1 = __ldg(off + v + 1);
    float4 t = ((const float4*)attn)[lane];
    float4 r = ((const float4*)(er + (size_t)v * FD))[lane];

    float4 acc = make_float4(0.f, 0.f, 0.f, 0.f);
    float den = 0.f;

    int i = i0;
    for (; i + 2 <= i1; i += 2) {
        int u0 = __ldg(csr + i), u1 = __ldg(csr + i + 1);
        float4 a0 = ((const float4*)(el + (size_t)u0 * FD))[lane];
        float4 a1 = ((const float4*)(el + (size_t)u1 * FD))[lane];
        float p0 = lrelu(a0.x + r.x, 0.2f) * t.x + lrelu(a0.y + r.y, 0.2f) * t.y
                 + lrelu(a0.z + r.z, 0.2f) * t.z + lrelu(a0.w + r.w, 0.2f) * t.w;
        float p1 = lrelu(a1.x + r.x, 0.2f) * t.x + lrelu(a1.y + r.y, 0.2f) * t.y
                 + lrelu(a1.z + r.z, 0.2f) * t.z + lrelu(a1.w + r.w, 0.2f) * t.w;
#pragma unroll
        for (int o = 16; o; o >>= 1) {
            p0 += __shfl_xor_sync(0xffffffffu, p0, o);
            p1 += __shfl_xor_sync(0xffffffffu, p1, o);
        }
        float e0 = expf(p0), e1 = expf(p1);
        den += e0 + e1;
        acc.x += e0 * a0.x + e1 * a1.x;
        acc.y += e0 * a0.y + e1 * a1.y;
        acc.z += e0 * a0.z + e1 * a1.z;
        acc.w += e0 * a0.w + e1 * a1.w;
    }
    if (i < i1) {
        int u0 = __ldg(csr + i);
        float4 a0 = ((const float4*)(el + (size_t)u0 * FD))[lane];
        float p0 = lrelu(a0.x + r.x, 0.2f) * t.x + lrelu(a0.y + r.y, 0.2f) * t.y
                 + lrelu(a0.z + r.z, 0.2f) * t.z + lrelu(a0.w + r.w, 0.2f) * t.w;
#pragma unroll
        for (int o = 16; o; o >>= 1) p0 += __shfl_xor_sync(0xffffffffu, p0, o);
        float e0 = expf(p0);
        den += e0;
        acc.x += e0 * a0.x; acc.y += e0 * a0.y;
        acc.z += e0 * a0.z; acc.w += e0 * a0.w;
    }

    float inv = (i1 > i0) ? (1.f / den) : 0.f;
    acc.x = lrelu(acc.x * inv, 0.01f);
    acc.y = lrelu(acc.y * inv, 0.01f);
    acc.z = lrelu(acc.z * inv, 0.01f);
    acc.w = lrelu(acc.w * inv, 0.01f);

    if (LAYER == 2) {
        ((float4*)(out + (size_t)v * FD))[lane] = acc;
    } else {
        ((float4*)(g_h1 + (size_t)v * FD))[lane] = acc;
        float sum = acc.x + acc.y + acc.z + acc.w;
#pragma unroll
        for (int o = 16; o; o >>= 1) sum += __shfl_xor_sync(0xffffffffu, sum, o);
        if (lane == 0 && sum != 0.f) g_map[__ldg(nid + v)] = v;
    }
}

// ---------------- launch -----------------------------------------------------
extern "C" void kernel_launch(void* const* d_in, const int* in_sizes, int n_in,
                              void* d_out, int out_size)
{
    const float* emb     = (const float*)d_in[0];
    const int*   i2u_src = (const int*)d_in[1];
    const int*   i2u_dst = (const int*)d_in[2];
    const int*   i2u_nid = (const int*)d_in[3];
    const int*   soc_src = (const int*)d_in[4];
    const int*   soc_dst = (const int*)d_in[5];
    const float* Ws1 = (const float*)d_in[6];
    const float* bs1 = (const float*)d_in[7];
    const float* Wd1 = (const float*)d_in[8];
    const float* bd1 = (const float*)d_in[9];
    const float* at1 = (const float*)d_in[10];
    const float* Ws2 = (const float*)d_in[11];
    const float* bs2 = (const float*)d_in[12];
    const float* Wd2 = (const float*)d_in[13];
    const float* bd2 = (const float*)d_in[14];
    const float* at2 = (const float*)d_in[15];
    float* out = (float*)d_out;

    const int E1 = in_sizes[1];
    const int E2 = in_sizes[4];
    const int N1 = in_sizes[3];
    const int NS = out_size / FD;

    int* cnt1 = nullptr; int* cnt2 = nullptr;
    int* off1 = nullptr; int* off2 = nullptr;
    int* csr1 = nullptr; int* csr2 = nullptr;
    int* cs1  = nullptr; int* cs2  = nullptr;
    cudaGetSymbolAddress((void**)&cnt1, g_cnt1);
    cudaGetSymbolAddress((void**)&cnt2, g_cnt2);
    cudaGetSymbolAddress((void**)&off1, g_off1);
    cudaGetSymbolAddress((void**)&off2, g_off2);
    cudaGetSymbolAddress((void**)&csr1, g_csr1);
    cudaGetSymbolAddress((void**)&csr2, g_csr2);
    cudaGetSymbolAddress((void**)&cs1,  g_csum1);
    cudaGetSymbolAddress((void**)&cs2,  g_csum2);

    const int ch1 = (N1 + 1023) / 1024;
    const int ch2 = (NS + 1023) / 1024;

    // 0) init
    k_init<<<(cNSOC + 255) / 256, 256>>>();

    // 1) CSR builds (both graphs)
    k_hist<<<(E1 + 255) / 256, 256>>>(i2u_dst, cnt1, E1);
    k_hist<<<(E2 + 255) / 256, 256>>>(soc_dst, cnt2, E2);
    k_scanA<<<ch1, 1024>>>(cnt1, off1, cs1, N1);
    k_scanA<<<ch2, 1024>>>(cnt2, off2, cs2, NS);
    k_scanB<<<1, 128>>>(cs1, ch1);
    k_scanB<<<1, 128>>>(cs2, ch2);
    k_scanC<<<(N1 + 255) / 256, 256>>>(off1, cs1, N1);
    k_scanC<<<(NS + 255) / 256, 256>>>(off2, cs2, NS);
    k_cursor<<<(N1 + 255) / 256, 256>>>(cnt1, off1, N1);
    k_cursor<<<(NS + 255) / 256, 256>>>(cnt2, off2, NS);
    k_scatter<<<(E1 + 255) / 256, 256>>>(i2u_src, i2u_dst, cnt1, csr1, E1);
    k_scatter<<<(E2 + 255) / 256, 256>>>(soc_src, soc_dst, cnt2, csr2, E2);

    // 2) layer 1: projections + fused per-node aggregation (writes h1, map)
    k_gemm2<1><<<(N1 + 63) / 64, 256>>>(emb, i2u_nid, Ws1, bs1, Wd1, bd1, N1);
    k_node<1><<<(N1 + 7) / 8, 256>>>(at1, nullptr, i2u_nid, N1);

    // 3) layer 2: projections + fused aggregation straight into d_out
    k_gemm2<2><<<(NS + 63) / 64, 256>>>(emb, nullptr, Ws2, bs2, Wd2, bd2, NS);
    k_node<2><<<(NS + 7) / 8, 256>>>(at2, out, nullptr, NS);
}

// round 4
// speedup vs baseline: 2.1925x; 1.0578x over previous
#include <cuda_runtime.h>
#include <cstdint>

#define FD 128
#define F4 32

static const int cNSOC = 100000;
static const int cNI2U = 50000;
static const int cESOC = 1600000;
static const int cEI2U = 800000;

// ---------------- scratch ----------------------------------------------------
__device__ __align__(16) float g_el1[cNI2U * FD];
__device__ __align__(16) float g_er1[cNI2U * FD];
__device__ __align__(16) float g_el2[cNSOC * FD];
__device__ __align__(16) float g_er2[cNSOC * FD];
__device__ __align__(16) float g_h1 [cNI2U * FD];
__device__ int   g_map [cNSOC];
__device__ int   g_cnt1[cNI2U];
__device__ int   g_cnt2[cNSOC];
__device__ int   g_off1[cNI2U + 1];
__device__ int   g_off2[cNSOC + 1];
__device__ int   g_csr1[cEI2U];
__device__ int   g_csr2[cESOC];
__device__ int   g_csum1[64];
__device__ int   g_csum2[128];

__device__ __forceinline__ float lrelu(float x, float s) { return x > 0.f ? x : s * x; }

__device__ __forceinline__ unsigned tf32cvt(float x) {
    unsigned u;
    asm("cvt.rna.tf32.f32 %0, %1;" : "=r"(u) : "f"(x));
    return u;
}

// ---------------- init --------------------------------------------------------
__global__ void k_init() {
    int i = blockIdx.x * blockDim.x + threadIdx.x;
    if (i < cNSOC) { g_map[i] = -1; g_cnt2[i] = 0; }
    if (i < cNI2U) g_cnt1[i] = 0;
    if (i == 0) { g_off1[0] = 0; g_off2[0] = 0; }
}

// ---------------- CSR build ----------------------------------------------------
__global__ void k_hist(const int* __restrict__ dst, int* __restrict__ cnt, int E) {
    int e = blockIdx.x * blockDim.x + threadIdx.x;
    if (e < E) atomicAdd(cnt + __ldg(dst + e), 1);
}

__global__ void k_scanA(const int* __restrict__ cnt, int* __restrict__ off,
                        int* __restrict__ csum, int N) {
    __shared__ int sh[1024];
    int t = threadIdx.x;
    int i = blockIdx.x * 1024 + t;
    sh[t] = (i < N) ? cnt[i] : 0;
    __syncthreads();
#pragma unroll
    for (int d = 1; d < 1024; d <<= 1) {
        int add = (t >= d) ? sh[t - d] : 0;
        __syncthreads();
        sh[t] += add;
        __syncthreads();
    }
    if (i < N) off[i + 1] = sh[t];
    if (t == 1023) csum[blockIdx.x] = sh[t];
}

// two scans in one launch (block 0 -> csum1, block 1 -> csum2)
__global__ void k_scanB2(int* __restrict__ c1, int n1, int* __restrict__ c2, int n2) {
    __shared__ int sh[128];
    int* c = blockIdx.x ? c2 : c1;
    int n  = blockIdx.x ? n2 : n1;
    int t = threadIdx.x;
    sh[t] = (t < n) ? c[t] : 0;
    __syncthreads();
#pragma unroll
    for (int d = 1; d < 128; d <<= 1) {
        int add = (t >= d) ? sh[t - d] : 0;
        __syncthreads();
        sh[t] += add;
        __syncthreads();
    }
    if (t < n) c[t] = sh[t];
}

// finalize offsets AND write scatter cursor (cur aliases cnt)
__global__ void k_scanC(int* __restrict__ off, const int* __restrict__ csum,
                        int* __restrict__ cur, int N) {
    int i = blockIdx.x * blockDim.x + threadIdx.x;
    if (i >= N) return;
    int ch = i >> 10;
    int c = cur[i];                         // cnt[i]
    int inc = off[i + 1] + (ch > 0 ? csum[ch - 1] : 0);
    off[i + 1] = inc;
    cur[i] = inc - c;                       // exclusive prefix = start offset
}

__global__ void k_scatter(const int* __restrict__ src, const int* __restrict__ dst,
                          int* __restrict__ cur, int* __restrict__ csr, int E) {
    int e = blockIdx.x * blockDim.x + threadIdx.x;
    if (e >= E) return;
    int pos = atomicAdd(cur + __ldg(dst + e), 1);
    csr[pos] = __ldg(src + e);
}

// ---------------- tensor-core dual GEMM (3xTF32) -------------------------------
// el = feat@Ws+bs, er = feat@Wd+bd.  128 rows/block, 512 threads = 16 warps.
// warp w: mtile = w>>1 (16-row tile), half = w&1 (0->S, 1->D); n covered fully.
// mma.sync.m16n8k8.tf32 with hi/lo split: a*b ~= ah*bh + ah*bl + al*bh.
#define PF 132          // feat smem row pitch (floats)
#define PW 136          // W smem row pitch (floats)
#define KC 16           // k-chunk
#define GEMM_SMEM ((128 * PF + 4 * KC * PW) * 4)

#define MMA_TF32(ACC, A0, A1, A2, A3, B0, B1)                                   \
    asm volatile("mma.sync.aligned.m16n8k8.row.col.f32.tf32.tf32.f32 "          \
                 "{%0,%1,%2,%3}, {%4,%5,%6,%7}, {%8,%9}, {%0,%1,%2,%3};"        \
                 : "+f"(ACC[0]), "+f"(ACC[1]), "+f"(ACC[2]), "+f"(ACC[3])       \
                 : "r"(A0), "r"(A1), "r"(A2), "r"(A3), "r"(B0), "r"(B1))

template<int LAYER>
__global__ void __launch_bounds__(512, 1)
k_gemm_mma(const float* __restrict__ emb, const int* __restrict__ nid,
           const float* __restrict__ Ws, const float* __restrict__ bs,
           const float* __restrict__ Wd, const float* __restrict__ bd, int nrows)
{
    extern __shared__ float sm[];
    float* sf = sm;                     // [128][PF]
    float* sw = sm + 128 * PF;          // [4][KC][PW] : S_hi, S_lo, D_hi, D_lo

    float* outS = (LAYER == 1) ? g_el1 : g_el2;
    float* outD = (LAYER == 1) ? g_er1 : g_er2;

    const int tid = threadIdx.x;
    const int rowbase = blockIdx.x * 128;

    // gather 128-row feature tile
    for (int s = tid; s < 128 * F4; s += 512) {
        int r = s >> 5, c4 = s & 31;
        int g = rowbase + r;
        float4 v = make_float4(0.f, 0.f, 0.f, 0.f);
        if (g < nrows) {
            const float* p;
            if (LAYER == 1) {
                p = emb + (size_t)__ldg(nid + g) * FD;
            } else {
                int mj = g_map[g];
                p = (mj >= 0) ? (g_h1 + (size_t)mj * FD) : (emb + (size_t)g * FD);
            }
            v = ((const float4*)p)[c4];
        }
        ((float4*)(sf + r * PF))[c4] = v;
    }

    const int lane = tid & 31, warp = tid >> 5;
    const int mtile = warp >> 1, half = warp & 1;
    const int gid = lane >> 2, tig = lane & 3;

    float* swh = sw + half * (2 * KC * PW);
    float* swl = swh + KC * PW;

    float acc[16][4];
#pragma unroll
    for (int j = 0; j < 16; j++)
#pragma unroll
        for (int q = 0; q < 4; q++) acc[j][q] = 0.f;

    for (int ch = 0; ch < 8; ch++) {
        __syncthreads();
        // load + split W chunk (both S and D)
        for (int s = tid; s < KC * 32; s += 512) {
            int r = s >> 5, c4 = s & 31;
            float4 vs = ((const float4*)(Ws + (size_t)(ch * KC + r) * FD))[c4];
            float4 vd = ((const float4*)(Wd + (size_t)(ch * KC + r) * FD))[c4];
            uint4 h; float4 l; uint4 lb;
            h.x = tf32cvt(vs.x); l.x = vs.x - __uint_as_float(h.x); lb.x = tf32cvt(l.x);
            h.y = tf32cvt(vs.y); l.y = vs.y - __uint_as_float(h.y); lb.y = tf32cvt(l.y);
            h.z = tf32cvt(vs.z); l.z = vs.z - __uint_as_float(h.z); lb.z = tf32cvt(l.z);
            h.w = tf32cvt(vs.w); l.w = vs.w - __uint_as_float(h.w); lb.w = tf32cvt(l.w);
            ((uint4*)(sw + 0 * KC * PW + r * PW))[c4] = h;
            ((uint4*)(sw + 1 * KC * PW + r * PW))[c4] = lb;
            h.x = tf32cvt(vd.x); l.x = vd.x - __uint_as_float(h.x); lb.x = tf32cvt(l.x);
            h.y = tf32cvt(vd.y); l.y = vd.y - __uint_as_float(h.y); lb.y = tf32cvt(l.y);
            h.z = tf32cvt(vd.z); l.z = vd.z - __uint_as_float(h.z); lb.z = tf32cvt(l.z);
            h.w = tf32cvt(vd.w); l.w = vd.w - __uint_as_float(h.w); lb.w = tf32cvt(l.w);
            ((uint4*)(sw + 2 * KC * PW + r * PW))[c4] = h;
            ((uint4*)(sw + 3 * KC * PW + r * PW))[c4] = lb;
        }
        __syncthreads();

#pragma unroll
        for (int kk = 0; kk < KC; kk += 8) {
            int kcol = ch * KC + kk + tig;
            float a0f = sf[(mtile * 16 + gid    ) * PF + kcol];
            float a1f = sf[(mtile * 16 + gid + 8) * PF + kcol];
            float a2f = sf[(mtile * 16 + gid    ) * PF + kcol + 4];
            float a3f = sf[(mtile * 16 + gid + 8) * PF + kcol + 4];
            unsigned a0h = tf32cvt(a0f), a1h = tf32cvt(a1f);
            unsigned a2h = tf32cvt(a2f), a3h = tf32cvt(a3f);
            unsigned a0l = tf32cvt(a0f - __uint_as_float(a0h));
            unsigned a1l = tf32cvt(a1f - __uint_as_float(a1h));
            unsigned a2l = tf32cvt(a2f - __uint_as_float(a2h));
            unsigned a3l = tf32cvt(a3f - __uint_as_float(a3h));
#pragma unroll
            for (int j = 0; j < 16; j++) {
                unsigned b0h = __float_as_uint(swh[(kk + tig    ) * PW + j * 8 + gid]);
                unsigned b1h = __float_as_uint(swh[(kk + tig + 4) * PW + j * 8 + gid]);
                unsigned b0l = __float_as_uint(swl[(kk + tig    ) * PW + j * 8 + gid]);
                unsigned b1l = __float_as_uint(swl[(kk + tig + 4) * PW + j * 8 + gid]);
                MMA_TF32(acc[j], a0h, a1h, a2h, a3h, b0h, b1h);
                MMA_TF32(acc[j], a0h, a1h, a2h, a3h, b0l, b1l);
                MMA_TF32(acc[j], a0l, a1l, a2l, a3l, b0h, b1h);
            }
        }
    }

    // store with bias
    float* out = half ? outD : outS;
    const float* bias = half ? bd : bs;
    int r0 = rowbase + mtile * 16 + gid;
#pragma unroll
    for (int j = 0; j < 16; j++) {
        int col = j * 8 + tig * 2;
        float b0 = __ldg(bias + col), b1 = __ldg(bias + col + 1);
        if (r0 < nrows) {
            float2 v = make_float2(acc[j][0] + b0, acc[j][1] + b1);
            *(float2*)(out + (size_t)r0 * FD + col) = v;
        }
        if (r0 + 8 < nrows) {
            float2 v = make_float2(acc[j][2] + b0, acc[j][3] + b1);
            *(float2*)(out + (size_t)(r0 + 8) * FD + col) = v;
        }
    }
}

// ---------------- fused per-node GATv2 aggregation ------------------------------
template<int LAYER>
__global__ void __launch_bounds__(256)
k_node(const float* __restrict__ attn, float* __restrict__ out,
       const int* __restrict__ nid, int N)
{
    const float* el  = (LAYER == 1) ? g_el1  : g_el2;
    const float* er  = (LAYER == 1) ? g_er1  : g_er2;
    const int*   off = (LAYER == 1) ? g_off1 : g_off2;
    const int*   csr = (LAYER == 1) ? g_csr1 : g_csr2;

    int v    = (blockIdx.x * blockDim.x + threadIdx.x) >> 5;
    int lane = threadIdx.x & 31;
    if (v >= N) return;

    int i0 = __ldg(off + v), i1 = __ldg(off + v + 1);
    float4 t = ((const float4*)attn)[lane];
    float4 r = ((const float4*)(er + (size_t)v * FD))[lane];

    float4 acc = make_float4(0.f, 0.f, 0.f, 0.f);
    float den = 0.f;

    int i = i0;
    for (; i + 4 <= i1; i += 4) {
        int u0 = __ldg(csr + i),     u1 = __ldg(csr + i + 1);
        int u2 = __ldg(csr + i + 2), u3 = __ldg(csr + i + 3);
        float4 a0 = ((const float4*)(el + (size_t)u0 * FD))[lane];
        float4 a1 = ((const float4*)(el + (size_t)u1 * FD))[lane];
        float4 a2 = ((const float4*)(el + (size_t)u2 * FD))[lane];
        float4 a3 = ((const float4*)(el + (size_t)u3 * FD))[lane];
        float p0 = lrelu(a0.x + r.x, 0.2f) * t.x + lrelu(a0.y + r.y, 0.2f) * t.y
                 + lrelu(a0.z + r.z, 0.2f) * t.z + lrelu(a0.w + r.w, 0.2f) * t.w;
        float p1 = lrelu(a1.x + r.x, 0.2f) * t.x + lrelu(a1.y + r.y, 0.2f) * t.y
                 + lrelu(a1.z + r.z, 0.2f) * t.z + lrelu(a1.w + r.w, 0.2f) * t.w;
        float p2 = lrelu(a2.x + r.x, 0.2f) * t.x + lrelu(a2.y + r.y, 0.2f) * t.y
                 + lrelu(a2.z + r.z, 0.2f) * t.z + lrelu(a2.w + r.w, 0.2f) * t.w;
        float p3 = lrelu(a3.x + r.x, 0.2f) * t.x + lrelu(a3.y + r.y, 0.2f) * t.y
                 + lrelu(a3.z + r.z, 0.2f) * t.z + lrelu(a3.w + r.w, 0.2f) * t.w;
#pragma unroll
        for (int o = 16; o; o >>= 1) {
            p0 += __shfl_xor_sync(0xffffffffu, p0, o);
            p1 += __shfl_xor_sync(0xffffffffu, p1, o);
            p2 += __shfl_xor_sync(0xffffffffu, p2, o);
            p3 += __shfl_xor_sync(0xffffffffu, p3, o);
        }
        float e0 = expf(p0), e1 = expf(p1), e2 = expf(p2), e3 = expf(p3);
        den += (e0 + e1) + (e2 + e3);
        acc.x += e0 * a0.x + e1 * a1.x + e2 * a2.x + e3 * a3.x;
        acc.y += e0 * a0.y + e1 * a1.y + e2 * a2.y + e3 * a3.y;
        acc.z += e0 * a0.z + e1 * a1.z + e2 * a2.z + e3 * a3.z;
        acc.w += e0 * a0.w + e1 * a1.w + e2 * a2.w + e3 * a3.w;
    }
    for (; i < i1; i++) {
        int u0 = __ldg(csr + i);
        float4 a0 = ((const float4*)(el + (size_t)u0 * FD))[lane];
        float p0 = lrelu(a0.x + r.x, 0.2f) * t.x + lrelu(a0.y + r.y, 0.2f) * t.y
                 + lrelu(a0.z + r.z, 0.2f) * t.z + lrelu(a0.w + r.w, 0.2f) * t.w;
#pragma unroll
        for (int o = 16; o; o >>= 1) p0 += __shfl_xor_sync(0xffffffffu, p0, o);
        float e0 = expf(p0);
        den += e0;
        acc.x += e0 * a0.x; acc.y += e0 * a0.y;
        acc.z += e0 * a0.z; acc.w += e0 * a0.w;
    }

    float inv = (i1 > i0) ? (1.f / den) : 0.f;
    acc.x = lrelu(acc.x * inv, 0.01f);
    acc.y = lrelu(acc.y * inv, 0.01f);
    acc.z = lrelu(acc.z * inv, 0.01f);
    acc.w = lrelu(acc.w * inv, 0.01f);

    if (LAYER == 2) {
        ((float4*)(out + (size_t)v * FD))[lane] = acc;
    } else {
        ((float4*)(g_h1 + (size_t)v * FD))[lane] = acc;
        float sum = acc.x + acc.y + acc.z + acc.w;
#pragma unroll
        for (int o = 16; o; o >>= 1) sum += __shfl_xor_sync(0xffffffffu, sum, o);
        if (lane == 0 && sum != 0.f) g_map[__ldg(nid + v)] = v;
    }
}

// ---------------- launch ---------------------------------------------------------
extern "C" void kernel_launch(void* const* d_in, const int* in_sizes, int n_in,
                              void* d_out, int out_size)
{
    const float* emb     = (const float*)d_in[0];
    const int*   i2u_src = (const int*)d_in[1];
    const int*   i2u_dst = (const int*)d_in[2];
    const int*   i2u_nid = (const int*)d_in[3];
    const int*   soc_src = (const int*)d_in[4];
    const int*   soc_dst = (const int*)d_in[5];
    const float* Ws1 = (const float*)d_in[6];
    const float* bs1 = (const float*)d_in[7];
    const float* Wd1 = (const float*)d_in[8];
    const float* bd1 = (const float*)d_in[9];
    const float* at1 = (const float*)d_in[10];
    const float* Ws2 = (const float*)d_in[11];
    const float* bs2 = (const float*)d_in[12];
    const float* Wd2 = (const float*)d_in[13];
    const float* bd2 = (const float*)d_in[14];
    const float* at2 = (const float*)d_in[15];
    float* out = (float*)d_out;

    const int E1 = in_sizes[1];
    const int E2 = in_sizes[4];
    const int N1 = in_sizes[3];
    const int NS = out_size / FD;

    int *cnt1, *cnt2, *off1, *off2, *csr1, *csr2, *cs1, *cs2;
    cudaGetSymbolAddress((void**)&cnt1, g_cnt1);
    cudaGetSymbolAddress((void**)&cnt2, g_cnt2);
    cudaGetSymbolAddress((void**)&off1, g_off1);
    cudaGetSymbolAddress((void**)&off2, g_off2);
    cudaGetSymbolAddress((void**)&csr1, g_csr1);
    cudaGetSymbolAddress((void**)&csr2, g_csr2);
    cudaGetSymbolAddress((void**)&cs1,  g_csum1);
    cudaGetSymbolAddress((void**)&cs2,  g_csum2);

    static bool attr_done = false;
    if (!attr_done) {
        cudaFuncSetAttribute(k_gemm_mma<1>, cudaFuncAttributeMaxDynamicSharedMemorySize, GEMM_SMEM);
        cudaFuncSetAttribute(k_gemm_mma<2>, cudaFuncAttributeMaxDynamicSharedMemorySize, GEMM_SMEM);
        attr_done = true;
    }

    const int ch1 = (N1 + 1023) / 1024;
    const int ch2 = (NS + 1023) / 1024;

    k_init<<<(cNSOC + 255) / 256, 256>>>();

    k_hist<<<(E1 + 255) / 256, 256>>>(i2u_dst, cnt1, E1);
    k_hist<<<(E2 + 255) / 256, 256>>>(soc_dst, cnt2, E2);
    k_scanA<<<ch1, 1024>>>(cnt1, off1, cs1, N1);
    k_scanA<<<ch2, 1024>>>(cnt2, off2, cs2, NS);
    k_scanB2<<<2, 128>>>(cs1, ch1, cs2, ch2);
    k_scanC<<<(N1 + 255) / 256, 256>>>(off1, cs1, cnt1, N1);
    k_scanC<<<(NS + 255) / 256, 256>>>(off2, cs2, cnt2, NS);
    k_scatter<<<(E1 + 255) / 256, 256>>>(i2u_src, i2u_dst, cnt1, csr1, E1);
    k_scatter<<<(E2 + 255) / 256, 256>>>(soc_src, soc_dst, cnt2, csr2, E2);

    // layer 1
    k_gemm_mma<1><<<(N1 + 127) / 128, 512, GEMM_SMEM>>>(emb, i2u_nid, Ws1, bs1, Wd1, bd1, N1);
    k_node<1><<<(N1 + 7) / 8, 256>>>(at1, nullptr, i2u_nid, N1);

    // layer 2
    k_gemm_mma<2><<<(NS + 127) / 128, 512, GEMM_SMEM>>>(emb, nullptr, Ws2, bs2, Wd2, bd2, NS);
    k_node<2><<<(NS + 7) / 8, 256>>>(at2, out, nullptr, NS);
}

// round 5
// speedup vs baseline: 2.3496x; 1.0717x over previous
#include <cuda_runtime.h>
#include <cstdint>

#define FD 128
#define F4 32

static const int cNSOC = 100000;
static const int cNI2U = 50000;
static const int cESOC = 1600000;
static const int cEI2U = 800000;

// ---------------- scratch ----------------------------------------------------
__device__ __align__(16) float g_el1[cNI2U * FD];
__device__ __align__(16) float g_er1[cNI2U * FD];
__device__ __align__(16) float g_el2[cNSOC * FD];
__device__ __align__(16) float g_er2[cNSOC * FD];
__device__ __align__(16) float g_h1 [cNI2U * FD];
__device__ __align__(16) float g_wh[4][FD * FD];   // tf32 hi of Ws1,Wd1,Ws2,Wd2
__device__ __align__(16) float g_wl[4][FD * FD];   // tf32 lo
__device__ int   g_map [cNSOC];
__device__ int   g_cnt1[cNI2U];
__device__ int   g_cnt2[cNSOC];
__device__ int   g_off1[cNI2U + 1];
__device__ int   g_off2[cNSOC + 1];
__device__ int   g_csr1[cEI2U];
__device__ int   g_csr2[cESOC];
__device__ int   g_csum1[64];
__device__ int   g_csum2[128];

__device__ __forceinline__ float lrelu(float x, float s) { return x > 0.f ? x : s * x; }

__device__ __forceinline__ unsigned tf32cvt(float x) {
    unsigned u;
    asm("cvt.rna.tf32.f32 %0, %1;" : "=r"(u) : "f"(x));
    return u;
}

// ---------------- init (split per stream branch) ------------------------------
__global__ void k_init1() {
    int i = blockIdx.x * blockDim.x + threadIdx.x;
    if (i < cNSOC) g_map[i] = -1;
    if (i < cNI2U) g_cnt1[i] = 0;
    if (i == 0) g_off1[0] = 0;
}
__global__ void k_init2() {
    int i = blockIdx.x * blockDim.x + threadIdx.x;
    if (i < cNSOC) g_cnt2[i] = 0;
    if (i == 0) g_off2[0] = 0;
}

// ---------------- W split precompute ------------------------------------------
__global__ void k_wsplit(const float* __restrict__ W0, const float* __restrict__ W1,
                         const float* __restrict__ W2, const float* __restrict__ W3) {
    int i = blockIdx.x * blockDim.x + threadIdx.x;   // 0..65535
    int m = i >> 14, idx = i & 16383;
    const float* W = (m == 0) ? W0 : (m == 1) ? W1 : (m == 2) ? W2 : W3;
    float v = __ldg(W + idx);
    unsigned h = tf32cvt(v);
    g_wh[m][idx] = __uint_as_float(h);
    g_wl[m][idx] = __uint_as_float(tf32cvt(v - __uint_as_float(h)));
}

// ---------------- CSR build ----------------------------------------------------
__global__ void k_hist(const int* __restrict__ dst, int* __restrict__ cnt, int E) {
    int e = blockIdx.x * blockDim.x + threadIdx.x;
    if (e < E) atomicAdd(cnt + __ldg(dst + e), 1);
}

__global__ void k_scanA(const int* __restrict__ cnt, int* __restrict__ off,
                        int* __restrict__ csum, int N) {
    __shared__ int sh[1024];
    int t = threadIdx.x;
    int i = blockIdx.x * 1024 + t;
    sh[t] = (i < N) ? cnt[i] : 0;
    __syncthreads();
#pragma unroll
    for (int d = 1; d < 1024; d <<= 1) {
        int add = (t >= d) ? sh[t - d] : 0;
        __syncthreads();
        sh[t] += add;
        __syncthreads();
    }
    if (i < N) off[i + 1] = sh[t];
    if (t == 1023) csum[blockIdx.x] = sh[t];
}

__global__ void k_scanB(int* __restrict__ c, int n) {
    __shared__ int sh[128];
    int t = threadIdx.x;
    sh[t] = (t < n) ? c[t] : 0;
    __syncthreads();
#pragma unroll
    for (int d = 1; d < 128; d <<= 1) {
        int add = (t >= d) ? sh[t - d] : 0;
        __syncthreads();
        sh[t] += add;
        __syncthreads();
    }
    if (t < n) c[t] = sh[t];
}

__global__ void k_scanC(int* __restrict__ off, const int* __restrict__ csum,
                        int* __restrict__ cur, int N) {
    int i = blockIdx.x * blockDim.x + threadIdx.x;
    if (i >= N) return;
    int ch = i >> 10;
    int c = cur[i];
    int inc = off[i + 1] + (ch > 0 ? csum[ch - 1] : 0);
    off[i + 1] = inc;
    cur[i] = inc - c;
}

__global__ void k_scatter(const int* __restrict__ src, const int* __restrict__ dst,
                          int* __restrict__ cur, int* __restrict__ csr, int E) {
    int e = blockIdx.x * blockDim.x + threadIdx.x;
    if (e >= E) return;
    int pos = atomicAdd(cur + __ldg(dst + e), 1);
    csr[pos] = __ldg(src + e);
}

// ---------------- tensor-core dual GEMM (3xTF32, pre-split W) -------------------
#define PF 132
#define PW 136
#define KC 32
#define GEMM_SMEM ((128 * PF + 4 * KC * PW) * 4)

#define MMA_TF32(ACC, A0, A1, A2, A3, B0, B1)                                   \
    asm volatile("mma.sync.aligned.m16n8k8.row.col.f32.tf32.tf32.f32 "          \
                 "{%0,%1,%2,%3}, {%4,%5,%6,%7}, {%8,%9}, {%0,%1,%2,%3};"        \
                 : "+f"(ACC[0]), "+f"(ACC[1]), "+f"(ACC[2]), "+f"(ACC[3])       \
                 : "r"(A0), "r"(A1), "r"(A2), "r"(A3), "r"(B0), "r"(B1))

template<int LAYER>
__global__ void __launch_bounds__(512, 1)
k_gemm_mma(const float* __restrict__ emb, const int* __restrict__ nid,
           const float* __restrict__ bs, const float* __restrict__ bd, int nrows)
{
    extern __shared__ float sm[];
    float* sf = sm;                     // [128][PF] fp32 features
    float* sw = sm + 128 * PF;          // [4][KC][PW] : S_hi, S_lo, D_hi, D_lo

    const int mS = (LAYER == 1) ? 0 : 2;
    const int mD = (LAYER == 1) ? 1 : 3;
    float* outS = (LAYER == 1) ? g_el1 : g_el2;
    float* outD = (LAYER == 1) ? g_er1 : g_er2;

    const int tid = threadIdx.x;
    const int rowbase = blockIdx.x * 128;

    // gather 128-row feature tile
    for (int s = tid; s < 128 * F4; s += 512) {
        int r = s >> 5, c4 = s & 31;
        int g = rowbase + r;
        float4 v = make_float4(0.f, 0.f, 0.f, 0.f);
        if (g < nrows) {
            const float* p;
            if (LAYER == 1) {
                p = emb + (size_t)__ldg(nid + g) * FD;
            } else {
                int mj = g_map[g];
                p = (mj >= 0) ? (g_h1 + (size_t)mj * FD) : (emb + (size_t)g * FD);
            }
            v = ((const float4*)p)[c4];
        }
        ((float4*)(sf + r * PF))[c4] = v;
    }

    const int lane = tid & 31, warp = tid >> 5;
    const int mtile = warp >> 1, half = warp & 1;
    const int gid = lane >> 2, tig = lane & 3;

    float* swh = sw + half * (2 * KC * PW);
    float* swl = swh + KC * PW;

    float acc[16][4];
#pragma unroll
    for (int j = 0; j < 16; j++)
#pragma unroll
        for (int q = 0; q < 4; q++) acc[j][q] = 0.f;

    for (int ch = 0; ch < 4; ch++) {
        __syncthreads();
        // stage pre-split W chunk (pure copies, no conversion)
        for (int s = tid; s < KC * 32; s += 512) {
            int r = s >> 5, c4 = s & 31;
            size_t goff = (size_t)(ch * KC + r) * FD;
            ((float4*)(sw + 0 * KC * PW + r * PW))[c4] = ((const float4*)(g_wh[mS] + goff))[c4];
            ((float4*)(sw + 1 * KC * PW + r * PW))[c4] = ((const float4*)(g_wl[mS] + goff))[c4];
            ((float4*)(sw + 2 * KC * PW + r * PW))[c4] = ((const float4*)(g_wh[mD] + goff))[c4];
            ((float4*)(sw + 3 * KC * PW + r * PW))[c4] = ((const float4*)(g_wl[mD] + goff))[c4];
        }
        __syncthreads();

#pragma unroll
        for (int kk = 0; kk < KC; kk += 8) {
            int kcol = ch * KC + kk + tig;
            float a0f = sf[(mtile * 16 + gid    ) * PF + kcol];
            float a1f = sf[(mtile * 16 + gid + 8) * PF + kcol];
            float a2f = sf[(mtile * 16 + gid    ) * PF + kcol + 4];
            float a3f = sf[(mtile * 16 + gid + 8) * PF + kcol + 4];
            unsigned a0h = tf32cvt(a0f), a1h = tf32cvt(a1f);
            unsigned a2h = tf32cvt(a2f), a3h = tf32cvt(a3f);
            unsigned a0l = tf32cvt(a0f - __uint_as_float(a0h));
            unsigned a1l = tf32cvt(a1f - __uint_as_float(a1h));
            unsigned a2l = tf32cvt(a2f - __uint_as_float(a2h));
            unsigned a3l = tf32cvt(a3f - __uint_as_float(a3h));
#pragma unroll
            for (int j = 0; j < 16; j++) {
                unsigned b0h = __float_as_uint(swh[(kk + tig    ) * PW + j * 8 + gid]);
                unsigned b1h = __float_as_uint(swh[(kk + tig + 4) * PW + j * 8 + gid]);
                unsigned b0l = __float_as_uint(swl[(kk + tig    ) * PW + j * 8 + gid]);
                unsigned b1l = __float_as_uint(swl[(kk + tig + 4) * PW + j * 8 + gid]);
                MMA_TF32(acc[j], a0h, a1h, a2h, a3h, b0h, b1h);
                MMA_TF32(acc[j], a0h, a1h, a2h, a3h, b0l, b1l);
                MMA_TF32(acc[j], a0l, a1l, a2l, a3l, b0h, b1h);
            }
        }
    }

    float* out = half ? outD : outS;
    const float* bias = half ? bd : bs;
    int r0 = rowbase + mtile * 16 + gid;
#pragma unroll
    for (int j = 0; j < 16; j++) {
        int col = j * 8 + tig * 2;
        float b0 = __ldg(bias + col), b1 = __ldg(bias + col + 1);
        if (r0 < nrows) {
            *(float2*)(out + (size_t)r0 * FD + col) =
                make_float2(acc[j][0] + b0, acc[j][1] + b1);
        }
        if (r0 + 8 < nrows) {
            *(float2*)(out + (size_t)(r0 + 8) * FD + col) =
                make_float2(acc[j][2] + b0, acc[j][3] + b1);
        }
    }
}

// ---------------- fused per-node GATv2 aggregation ------------------------------
template<int LAYER>
__global__ void __launch_bounds__(256)
k_node(const float* __restrict__ attn, float* __restrict__ out,
       const int* __restrict__ nid, int N)
{
    const float* el  = (LAYER == 1) ? g_el1  : g_el2;
    const float* er  = (LAYER == 1) ? g_er1  : g_er2;
    const int*   off = (LAYER == 1) ? g_off1 : g_off2;
    const int*   csr = (LAYER == 1) ? g_csr1 : g_csr2;

    int v    = (blockIdx.x * blockDim.x + threadIdx.x) >> 5;
    int lane = threadIdx.x & 31;
    if (v >= N) return;

    int i0 = __ldg(off + v), i1 = __ldg(off + v + 1);
    float4 t = ((const float4*)attn)[lane];
    float4 r = ((const float4*)(er + (size_t)v * FD))[lane];

    float4 acc = make_float4(0.f, 0.f, 0.f, 0.f);
    float den = 0.f;

    int i = i0;
    for (; i + 4 <= i1; i += 4) {
        int u0 = __ldg(csr + i),     u1 = __ldg(csr + i + 1);
        int u2 = __ldg(csr + i + 2), u3 = __ldg(csr + i + 3);
        float4 a0 = ((const float4*)(el + (size_t)u0 * FD))[lane];
        float4 a1 = ((const float4*)(el + (size_t)u1 * FD))[lane];
        float4 a2 = ((const float4*)(el + (size_t)u2 * FD))[lane];
        float4 a3 = ((const float4*)(el + (size_t)u3 * FD))[lane];
        float p0 = lrelu(a0.x + r.x, 0.2f) * t.x + lrelu(a0.y + r.y, 0.2f) * t.y
                 + lrelu(a0.z + r.z, 0.2f) * t.z + lrelu(a0.w + r.w, 0.2f) * t.w;
        float p1 = lrelu(a1.x + r.x, 0.2f) * t.x + lrelu(a1.y + r.y, 0.2f) * t.y
                 + lrelu(a1.z + r.z, 0.2f) * t.z + lrelu(a1.w + r.w, 0.2f) * t.w;
        float p2 = lrelu(a2.x + r.x, 0.2f) * t.x + lrelu(a2.y + r.y, 0.2f) * t.y
                 + lrelu(a2.z + r.z, 0.2f) * t.z + lrelu(a2.w + r.w, 0.2f) * t.w;
        float p3 = lrelu(a3.x + r.x, 0.2f) * t.x + lrelu(a3.y + r.y, 0.2f) * t.y
                 + lrelu(a3.z + r.z, 0.2f) * t.z + lrelu(a3.w + r.w, 0.2f) * t.w;
#pragma unroll
        for (int o = 16; o; o >>= 1) {
            p0 += __shfl_xor_sync(0xffffffffu, p0, o);
            p1 += __shfl_xor_sync(0xffffffffu, p1, o);
            p2 += __shfl_xor_sync(0xffffffffu, p2, o);
            p3 += __shfl_xor_sync(0xffffffffu, p3, o);
        }
        float e0 = expf(p0), e1 = expf(p1), e2 = expf(p2), e3 = expf(p3);
        den += (e0 + e1) + (e2 + e3);
        acc.x += e0 * a0.x + e1 * a1.x + e2 * a2.x + e3 * a3.x;
        acc.y += e0 * a0.y + e1 * a1.y + e2 * a2.y + e3 * a3.y;
        acc.z += e0 * a0.z + e1 * a1.z + e2 * a2.z + e3 * a3.z;
        acc.w += e0 * a0.w + e1 * a1.w + e2 * a2.w + e3 * a3.w;
    }
    for (; i < i1; i++) {
        int u0 = __ldg(csr + i);
        float4 a0 = ((const float4*)(el + (size_t)u0 * FD))[lane];
        float p0 = lrelu(a0.x + r.x, 0.2f) * t.x + lrelu(a0.y + r.y, 0.2f) * t.y
                 + lrelu(a0.z + r.z, 0.2f) * t.z + lrelu(a0.w + r.w, 0.2f) * t.w;
#pragma unroll
        for (int o = 16; o; o >>= 1) p0 += __shfl_xor_sync(0xffffffffu, p0, o);
        float e0 = expf(p0);
        den += e0;
        acc.x += e0 * a0.x; acc.y += e0 * a0.y;
        acc.z += e0 * a0.z; acc.w += e0 * a0.w;
    }

    float inv = (i1 > i0) ? (1.f / den) : 0.f;
    acc.x = lrelu(acc.x * inv, 0.01f);
    acc.y = lrelu(acc.y * inv, 0.01f);
    acc.z = lrelu(acc.z * inv, 0.01f);
    acc.w = lrelu(acc.w * inv, 0.01f);

    if (LAYER == 2) {
        ((float4*)(out + (size_t)v * FD))[lane] = acc;
    } else {
        ((float4*)(g_h1 + (size_t)v * FD))[lane] = acc;
        float sum = acc.x + acc.y + acc.z + acc.w;
#pragma unroll
        for (int o = 16; o; o >>= 1) sum += __shfl_xor_sync(0xffffffffu, sum, o);
        if (lane == 0 && sum != 0.f) g_map[__ldg(nid + v)] = v;
    }
}

// ---------------- launch ---------------------------------------------------------
extern "C" void kernel_launch(void* const* d_in, const int* in_sizes, int n_in,
                              void* d_out, int out_size)
{
    const float* emb     = (const float*)d_in[0];
    const int*   i2u_src = (const int*)d_in[1];
    const int*   i2u_dst = (const int*)d_in[2];
    const int*   i2u_nid = (const int*)d_in[3];
    const int*   soc_src = (const int*)d_in[4];
    const int*   soc_dst = (const int*)d_in[5];
    const float* Ws1 = (const float*)d_in[6];
    const float* bs1 = (const float*)d_in[7];
    const float* Wd1 = (const float*)d_in[8];
    const float* bd1 = (const float*)d_in[9];
    const float* at1 = (const float*)d_in[10];
    const float* Ws2 = (const float*)d_in[11];
    const float* bs2 = (const float*)d_in[12];
    const float* Wd2 = (const float*)d_in[13];
    const float* bd2 = (const float*)d_in[14];
    const float* at2 = (const float*)d_in[15];
    float* out = (float*)d_out;

    const int E1 = in_sizes[1];
    const int E2 = in_sizes[4];
    const int N1 = in_sizes[3];
    const int NS = out_size / FD;

    int *cnt1, *cnt2, *off1, *off2, *csr1, *csr2, *cs1, *cs2;
    cudaGetSymbolAddress((void**)&cnt1, g_cnt1);
    cudaGetSymbolAddress((void**)&cnt2, g_cnt2);
    cudaGetSymbolAddress((void**)&off1, g_off1);
    cudaGetSymbolAddress((void**)&off2, g_off2);
    cudaGetSymbolAddress((void**)&csr1, g_csr1);
    cudaGetSymbolAddress((void**)&csr2, g_csr2);
    cudaGetSymbolAddress((void**)&cs1,  g_csum1);
    cudaGetSymbolAddress((void**)&cs2,  g_csum2);

    static cudaStream_t s1 = nullptr, s2 = nullptr;
    static cudaEvent_t ev0 = nullptr, ev1 = nullptr, ev2 = nullptr;
    if (!s1) {
        cudaStreamCreateWithFlags(&s1, cudaStreamNonBlocking);
        cudaStreamCreateWithFlags(&s2, cudaStreamNonBlocking);
        cudaEventCreateWithFlags(&ev0, cudaEventDisableTiming);
        cudaEventCreateWithFlags(&ev1, cudaEventDisableTiming);
        cudaEventCreateWithFlags(&ev2, cudaEventDisableTiming);
        cudaFuncSetAttribute(k_gemm_mma<1>, cudaFuncAttributeMaxDynamicSharedMemorySize, GEMM_SMEM);
        cudaFuncSetAttribute(k_gemm_mma<2>, cudaFuncAttributeMaxDynamicSharedMemorySize, GEMM_SMEM);
    }

    const int ch1 = (N1 + 1023) / 1024;
    const int ch2 = (NS + 1023) / 1024;

    // fork side branches off the (captured) main stream
    cudaEventRecord(ev0, 0);
    cudaStreamWaitEvent(s1, ev0, 0);
    cudaStreamWaitEvent(s2, ev0, 0);

    // branch s1: graph-1 CSR + map init
    k_init1<<<(cNSOC + 255) / 256, 256, 0, s1>>>();
    k_hist<<<(E1 + 255) / 256, 256, 0, s1>>>(i2u_dst, cnt1, E1);
    k_scanA<<<ch1, 1024, 0, s1>>>(cnt1, off1, cs1, N1);
    k_scanB<<<1, 128, 0, s1>>>(cs1, ch1);
    k_scanC<<<(N1 + 255) / 256, 256, 0, s1>>>(off1, cs1, cnt1, N1);
    k_scatter<<<(E1 + 255) / 256, 256, 0, s1>>>(i2u_src, i2u_dst, cnt1, csr1, E1);
    cudaEventRecord(ev1, s1);

    // branch s2: graph-2 CSR
    k_init2<<<(cNSOC + 255) / 256, 256, 0, s2>>>();
    k_hist<<<(E2 + 255) / 256, 256, 0, s2>>>(soc_dst, cnt2, E2);
    k_scanA<<<ch2, 1024, 0, s2>>>(cnt2, off2, cs2, NS);
    k_scanB<<<1, 128, 0, s2>>>(cs2, ch2);
    k_scanC<<<(NS + 255) / 256, 256, 0, s2>>>(off2, cs2, cnt2, NS);
    k_scatter<<<(E2 + 255) / 256, 256, 0, s2>>>(soc_src, soc_dst, cnt2, csr2, E2);
    cudaEventRecord(ev2, s2);

    // main stream: W split, then layer-1 GEMM (independent of CSR)
    k_wsplit<<<256, 256>>>(Ws1, Wd1, Ws2, Wd2);
    k_gemm_mma<1><<<(N1 + 127) / 128, 512, GEMM_SMEM>>>(emb, i2u_nid, bs1, bd1, N1);

    // join graph-1 CSR, aggregate layer 1
    cudaStreamWaitEvent(0, ev1, 0);
    k_node<1><<<(N1 + 7) / 8, 256>>>(at1, nullptr, i2u_nid, N1);

    // layer-2 GEMM (needs h1 + map)
    k_gemm_mma<2><<<(NS + 127) / 128, 512, GEMM_SMEM>>>(emb, nullptr, bs2, bd2, NS);

    // join graph-2 CSR, aggregate layer 2 into d_out
    cudaStreamWaitEvent(0, ev2, 0);
    k_node<2><<<(NS + 7) / 8, 256>>>(at2, out, nullptr, NS);
}

// round 6
// speedup vs baseline: 2.5285x; 1.0761x over previous
#include <cuda_runtime.h>
#include <cuda_bf16.h>
#include <cstdint>

#define FD 128
#define F4 32

static const int cNSOC = 100000;
static const int cNI2U = 50000;
static const int cESOC = 1600000;
static const int cEI2U = 800000;

// ---------------- scratch ----------------------------------------------------
__device__ __align__(16) float g_el1[cNI2U * FD];
__device__ __align__(16) float g_er1[cNI2U * FD];
__device__ __align__(16) float g_el2[cNSOC * FD];
__device__ __align__(16) float g_er2[cNSOC * FD];
__device__ __align__(16) float g_h1 [cNI2U * FD];
__device__ __align__(16) __nv_bfloat16 g_wbh[4][FD * FD];  // bf16 hi, transposed [n][k]
__device__ __align__(16) __nv_bfloat16 g_wbl[4][FD * FD];  // bf16 lo, transposed
__device__ int   g_map [cNSOC];
__device__ int   g_cnt1[cNI2U];
__device__ int   g_cnt2[cNSOC];
__device__ int   g_off1[cNI2U + 1];
__device__ int   g_off2[cNSOC + 1];
__device__ int   g_csr1[cEI2U];
__device__ int   g_csr2[cESOC];
__device__ int   g_csum1[64];
__device__ int   g_csum2[128];

__device__ __forceinline__ float lrelu(float x, float s) { return x > 0.f ? x : s * x; }

__device__ __forceinline__ void bf16split2(float x, float y, unsigned& hi, unsigned& lo) {
    __nv_bfloat162 h = __floats2bfloat162_rn(x, y);
    float rx = x - __bfloat162float(__low2bfloat16(h));
    float ry = y - __bfloat162float(__high2bfloat16(h));
    __nv_bfloat162 l = __floats2bfloat162_rn(rx, ry);
    hi = *(unsigned*)&h;
    lo = *(unsigned*)&l;
}

// non-allocating global load (random rows: no reuse, keep L1 for csr/er)
__device__ __forceinline__ float4 ldg4_na(const float4* p) {
    float4 v;
    asm volatile("ld.global.nc.L1::no_allocate.v4.f32 {%0,%1,%2,%3}, [%4];"
                 : "=f"(v.x), "=f"(v.y), "=f"(v.z), "=f"(v.w) : "l"(p));
    return v;
}

// ---------------- init ---------------------------------------------------------
__global__ void k_init1() {
    int i = blockIdx.x * blockDim.x + threadIdx.x;
    if (i < cNSOC) g_map[i] = -1;
    if (i < cNI2U) g_cnt1[i] = 0;
    if (i == 0) g_off1[0] = 0;
}
__global__ void k_init2() {
    int i = blockIdx.x * blockDim.x + threadIdx.x;
    if (i < cNSOC) g_cnt2[i] = 0;
    if (i == 0) g_off2[0] = 0;
}

// ---------------- W split: fp32 [k][n] -> bf16 hi/lo transposed [n][k] ---------
__global__ void k_wsplit(const float* __restrict__ W0, const float* __restrict__ W1,
                         const float* __restrict__ W2, const float* __restrict__ W3) {
    int i = blockIdx.x * blockDim.x + threadIdx.x;   // 0..65535
    int m = i >> 14, idx = i & 16383;
    int n = idx >> 7, k = idx & 127;
    const float* W = (m == 0) ? W0 : (m == 1) ? W1 : (m == 2) ? W2 : W3;
    float v = __ldg(W + k * FD + n);
    __nv_bfloat16 h = __float2bfloat16_rn(v);
    g_wbh[m][n * FD + k] = h;
    g_wbl[m][n * FD + k] = __float2bfloat16_rn(v - __bfloat162float(h));
}

// ---------------- CSR build ------------------------------------------------------
__global__ void k_hist(const int* __restrict__ dst, int* __restrict__ cnt, int E) {
    int e = blockIdx.x * blockDim.x + threadIdx.x;
    if (e < E) atomicAdd(cnt + __ldg(dst + e), 1);
}

__global__ void k_scanA(const int* __restrict__ cnt, int* __restrict__ off,
                        int* __restrict__ csum, int N) {
    __shared__ int sh[1024];
    int t = threadIdx.x;
    int i = blockIdx.x * 1024 + t;
    sh[t] = (i < N) ? cnt[i] : 0;
    __syncthreads();
#pragma unroll
    for (int d = 1; d < 1024; d <<= 1) {
        int add = (t >= d) ? sh[t - d] : 0;
        __syncthreads();
        sh[t] += add;
        __syncthreads();
    }
    if (i < N) off[i + 1] = sh[t];
    if (t == 1023) csum[blockIdx.x] = sh[t];
}

__global__ void k_scanB(int* __restrict__ c, int n) {
    __shared__ int sh[128];
    int t = threadIdx.x;
    sh[t] = (t < n) ? c[t] : 0;
    __syncthreads();
#pragma unroll
    for (int d = 1; d < 128; d <<= 1) {
        int add = (t >= d) ? sh[t - d] : 0;
        __syncthreads();
        sh[t] += add;
        __syncthreads();
    }
    if (t < n) c[t] = sh[t];
}

__global__ void k_scanC(int* __restrict__ off, const int* __restrict__ csum,
                        int* __restrict__ cur, int N) {
    int i = blockIdx.x * blockDim.x + threadIdx.x;
    if (i >= N) return;
    int ch = i >> 10;
    int c = cur[i];
    int inc = off[i + 1] + (ch > 0 ? csum[ch - 1] : 0);
    off[i + 1] = inc;
    cur[i] = inc - c;
}

__global__ void k_scatter(const int* __restrict__ src, const int* __restrict__ dst,
                          int* __restrict__ cur, int* __restrict__ csr, int E) {
    int e = blockIdx.x * blockDim.x + threadIdx.x;
    if (e >= E) return;
    int pos = atomicAdd(cur + __ldg(dst + e), 1);
    csr[pos] = __ldg(src + e);
}

// ---------------- tensor-core dual GEMM (bf16x3 split) ---------------------------
// el = feat@Ws+bs, er = feat@Wd+bd.  128 rows/block, 512 threads = 16 warps.
// warp w: mtile = w>>1, half = w&1 (0->S, 1->D).
// m16n8k16 bf16 MMA; a ~= a0+a1, b ~= b0+b1; D += a0b0 + a0b1 + a1b0.
#define PA 66           // A smem pitch in 32-bit words (kpairs)
#define PB 20           // W smem pitch in 32-bit words
#define GEMM_SMEM ((2 * 128 * PA + 4 * 128 * PB) * 4)

#define MMA_BF16(ACC, A, B0, B1)                                                \
    asm volatile("mma.sync.aligned.m16n8k16.row.col.f32.bf16.bf16.f32 "         \
                 "{%0,%1,%2,%3}, {%4,%5,%6,%7}, {%8,%9}, {%0,%1,%2,%3};"        \
                 : "+f"(ACC[0]), "+f"(ACC[1]), "+f"(ACC[2]), "+f"(ACC[3])       \
                 : "r"(A[0]), "r"(A[1]), "r"(A[2]), "r"(A[3]), "r"(B0), "r"(B1))

template<int LAYER>
__global__ void __launch_bounds__(512, 1)
k_gemm_mma(const float* __restrict__ emb, const int* __restrict__ nid,
           const float* __restrict__ bs, const float* __restrict__ bd, int nrows)
{
    extern __shared__ unsigned smu[];
    unsigned* sf0 = smu;                   // [128][PA] bf16x2 words (hi)
    unsigned* sf1 = sf0 + 128 * PA;        // (lo)
    unsigned* sw  = sf1 + 128 * PA;        // [mat][split][128][PB]

    const int mS = (LAYER == 1) ? 0 : 2;
    const int mD = (LAYER == 1) ? 1 : 3;
    float* outS = (LAYER == 1) ? g_el1 : g_el2;
    float* outD = (LAYER == 1) ? g_er1 : g_er2;

    const int tid = threadIdx.x;
    const int rowbase = blockIdx.x * 128;

    // gather 128-row feature tile, split to bf16 hi/lo in smem
    for (int s = tid; s < 128 * F4; s += 512) {
        int r = s >> 5, c4 = s & 31;
        int g = rowbase + r;
        float4 v = make_float4(0.f, 0.f, 0.f, 0.f);
        if (g < nrows) {
            const float* p;
            if (LAYER == 1) {
                p = emb + (size_t)__ldg(nid + g) * FD;
            } else {
                int mj = g_map[g];
                p = (mj >= 0) ? (g_h1 + (size_t)mj * FD) : (emb + (size_t)g * FD);
            }
            v = ((const float4*)p)[c4];
        }
        unsigned h0, l0, h1, l1;
        bf16split2(v.x, v.y, h0, l0);
        bf16split2(v.z, v.w, h1, l1);
        int w = r * PA + c4 * 2;
        sf0[w] = h0; sf0[w + 1] = h1;
        sf1[w] = l0; sf1[w + 1] = l1;
    }

    const int lane = tid & 31, warp = tid >> 5;
    const int mtile = warp >> 1, half = warp & 1;
    const int gid = lane >> 2, tig = lane & 3;

    unsigned* swh = sw + (half * 2 + 0) * 128 * PB;
    unsigned* swl = sw + (half * 2 + 1) * 128 * PB;

    float acc[16][4];
#pragma unroll
    for (int j = 0; j < 16; j++)
#pragma unroll
        for (int q = 0; q < 4; q++) acc[j][q] = 0.f;

    const __nv_bfloat16* wbhS = g_wbh[mS];
    const __nv_bfloat16* wblS = g_wbl[mS];
    const __nv_bfloat16* wbhD = g_wbh[mD];
    const __nv_bfloat16* wblD = g_wbl[mD];

    for (int ch = 0; ch < 4; ch++) {
        __syncthreads();
        // stage pre-split W chunk: rows n=0..127, k window [ch*32, ch*32+32)
        {
            int n = tid >> 2, q = tid & 3;           // 512 threads: exactly one each
            int gsrc = (n * FD + ch * 32) / 8 + q;   // uint4 units (8 bf16)
            int wdst = n * PB + q * 4;
            ((uint4*)(sw + 0 * 128 * PB + wdst))[0] = ((const uint4*)wbhS)[gsrc];
            ((uint4*)(sw + 1 * 128 * PB + wdst))[0] = ((const uint4*)wblS)[gsrc];
            ((uint4*)(sw + 2 * 128 * PB + wdst))[0] = ((const uint4*)wbhD)[gsrc];
            ((uint4*)(sw + 3 * 128 * PB + wdst))[0] = ((const uint4*)wblD)[gsrc];
        }
        __syncthreads();

#pragma unroll
        for (int kk = 0; kk < 2; kk++) {
            int kb = ch * 16 + kk * 8;       // global kpair base for this 16-k step
            int row0 = mtile * 16 + gid;
            unsigned A0[4], A1[4];
            A0[0] = sf0[ row0      * PA + kb + tig];
            A0[1] = sf0[(row0 + 8) * PA + kb + tig];
            A0[2] = sf0[ row0      * PA + kb + tig + 4];
            A0[3] = sf0[(row0 + 8) * PA + kb + tig + 4];
            A1[0] = sf1[ row0      * PA + kb + tig];
            A1[1] = sf1[(row0 + 8) * PA + kb + tig];
            A1[2] = sf1[ row0      * PA + kb + tig + 4];
            A1[3] = sf1[(row0 + 8) * PA + kb + tig + 4];
            int kl = kk * 8 + tig;           // local kpair within chunk
#pragma unroll
            for (int j = 0; j < 16; j++) {
                int n = j * 8 + gid;
                unsigned b0h = swh[n * PB + kl], b1h = swh[n * PB + kl + 4];
                unsigned b0l = swl[n * PB + kl], b1l = swl[n * PB + kl + 4];
                MMA_BF16(acc[j], A0, b0h, b1h);
                MMA_BF16(acc[j], A0, b0l, b1l);
                MMA_BF16(acc[j], A1, b0h, b1h);
            }
        }
    }

    float* out = half ? outD : outS;
    const float* bias = half ? bd : bs;
    int r0 = rowbase + mtile * 16 + gid;
#pragma unroll
    for (int j = 0; j < 16; j++) {
        int col = j * 8 + tig * 2;
        float b0 = __ldg(bias + col), b1 = __ldg(bias + col + 1);
        if (r0 < nrows) {
            *(float2*)(out + (size_t)r0 * FD + col) =
                make_float2(acc[j][0] + b0, acc[j][1] + b1);
        }
        if (r0 + 8 < nrows) {
            *(float2*)(out + (size_t)(r0 + 8) * FD + col) =
                make_float2(acc[j][2] + b0, acc[j][3] + b1);
        }
    }
}

// ---------------- fused per-node GATv2 aggregation --------------------------------
template<int LAYER>
__global__ void __launch_bounds__(256)
k_node(const float* __restrict__ attn, float* __restrict__ out,
       const int* __restrict__ nid, int N)
{
    const float* el  = (LAYER == 1) ? g_el1  : g_el2;
    const float* er  = (LAYER == 1) ? g_er1  : g_er2;
    const int*   off = (LAYER == 1) ? g_off1 : g_off2;
    const int*   csr = (LAYER == 1) ? g_csr1 : g_csr2;

    int v    = (blockIdx.x * blockDim.x + threadIdx.x) >> 5;
    int lane = threadIdx.x & 31;
    if (v >= N) return;

    int i0 = __ldg(off + v), i1 = __ldg(off + v + 1);
    float4 t = ((const float4*)attn)[lane];
    float4 r = ((const float4*)(er + (size_t)v * FD))[lane];

    float4 acc = make_float4(0.f, 0.f, 0.f, 0.f);
    float den = 0.f;

    int i = i0;
    for (; i + 4 <= i1; i += 4) {
        int u0 = __ldg(csr + i),     u1 = __ldg(csr + i + 1);
        int u2 = __ldg(csr + i + 2), u3 = __ldg(csr + i + 3);
        float4 a0 = ldg4_na((const float4*)(el + (size_t)u0 * FD) + lane);
        float4 a1 = ldg4_na((const float4*)(el + (size_t)u1 * FD) + lane);
        float4 a2 = ldg4_na((const float4*)(el + (size_t)u2 * FD) + lane);
        float4 a3 = ldg4_na((const float4*)(el + (size_t)u3 * FD) + lane);
        float p0 = lrelu(a0.x + r.x, 0.2f) * t.x + lrelu(a0.y + r.y, 0.2f) * t.y
                 + lrelu(a0.z + r.z, 0.2f) * t.z + lrelu(a0.w + r.w, 0.2f) * t.w;
        float p1 = lrelu(a1.x + r.x, 0.2f) * t.x + lrelu(a1.y + r.y, 0.2f) * t.y
                 + lrelu(a1.z + r.z, 0.2f) * t.z + lrelu(a1.w + r.w, 0.2f) * t.w;
        float p2 = lrelu(a2.x + r.x, 0.2f) * t.x + lrelu(a2.y + r.y, 0.2f) * t.y
                 + lrelu(a2.z + r.z, 0.2f) * t.z + lrelu(a2.w + r.w, 0.2f) * t.w;
        float p3 = lrelu(a3.x + r.x, 0.2f) * t.x + lrelu(a3.y + r.y, 0.2f) * t.y
                 + lrelu(a3.z + r.z, 0.2f) * t.z + lrelu(a3.w + r.w, 0.2f) * t.w;
#pragma unroll
        for (int o = 16; o; o >>= 1) {
            p0 += __shfl_xor_sync(0xffffffffu, p0, o);
            p1 += __shfl_xor_sync(0xffffffffu, p1, o);
            p2 += __shfl_xor_sync(0xffffffffu, p2, o);
            p3 += __shfl_xor_sync(0xffffffffu, p3, o);
        }
        float e0 = expf(p0), e1 = expf(p1), e2 = expf(p2), e3 = expf(p3);
        den += (e0 + e1) + (e2 + e3);
        acc.x += e0 * a0.x + e1 * a1.x + e2 * a2.x + e3 * a3.x;
        acc.y += e0 * a0.y + e1 * a1.y + e2 * a2.y + e3 * a3.y;
        acc.z += e0 * a0.z + e1 * a1.z + e2 * a2.z + e3 * a3.z;
        acc.w += e0 * a0.w + e1 * a1.w + e2 * a2.w + e3 * a3.w;
    }
    for (; i < i1; i++) {
        int u0 = __ldg(csr + i);
        float4 a0 = ldg4_na((const float4*)(el + (size_t)u0 * FD) + lane);
        float p0 = lrelu(a0.x + r.x, 0.2f) * t.x + lrelu(a0.y + r.y, 0.2f) * t.y
                 + lrelu(a0.z + r.z, 0.2f) * t.z + lrelu(a0.w + r.w, 0.2f) * t.w;
#pragma unroll
        for (int o = 16; o; o >>= 1) p0 += __shfl_xor_sync(0xffffffffu, p0, o);
        float e0 = expf(p0);
        den += e0;
        acc.x += e0 * a0.x; acc.y += e0 * a0.y;
        acc.z += e0 * a0.z; acc.w += e0 * a0.w;
    }

    float inv = (i1 > i0) ? (1.f / den) : 0.f;
    acc.x = lrelu(acc.x * inv, 0.01f);
    acc.y = lrelu(acc.y * inv, 0.01f);
    acc.z = lrelu(acc.z * inv, 0.01f);
    acc.w = lrelu(acc.w * inv, 0.01f);

    if (LAYER == 2) {
        ((float4*)(out + (size_t)v * FD))[lane] = acc;
    } else {
        ((float4*)(g_h1 + (size_t)v * FD))[lane] = acc;
        float sum = acc.x + acc.y + acc.z + acc.w;
#pragma unroll
        for (int o = 16; o; o >>= 1) sum += __shfl_xor_sync(0xffffffffu, sum, o);
        if (lane == 0 && sum != 0.f) g_map[__ldg(nid + v)] = v;
    }
}

// ---------------- launch ------------------------------------------------------------
extern "C" void kernel_launch(void* const* d_in, const int* in_sizes, int n_in,
                              void* d_out, int out_size)
{
    const float* emb     = (const float*)d_in[0];
    const int*   i2u_src = (const int*)d_in[1];
    const int*   i2u_dst = (const int*)d_in[2];
    const int*   i2u_nid = (const int*)d_in[3];
    const int*   soc_src = (const int*)d_in[4];
    const int*   soc_dst = (const int*)d_in[5];
    const float* Ws1 = (const float*)d_in[6];
    const float* bs1 = (const float*)d_in[7];
    const float* Wd1 = (const float*)d_in[8];
    const float* bd1 = (const float*)d_in[9];
    const float* at1 = (const float*)d_in[10];
    const float* Ws2 = (const float*)d_in[11];
    const float* bs2 = (const float*)d_in[12];
    const float* Wd2 = (const float*)d_in[13];
    const float* bd2 = (const float*)d_in[14];
    const float* at2 = (const float*)d_in[15];
    float* out = (float*)d_out;

    const int E1 = in_sizes[1];
    const int E2 = in_sizes[4];
    const int N1 = in_sizes[3];
    const int NS = out_size / FD;

    int *cnt1, *cnt2, *off1, *off2, *csr1, *csr2, *cs1, *cs2;
    cudaGetSymbolAddress((void**)&cnt1, g_cnt1);
    cudaGetSymbolAddress((void**)&cnt2, g_cnt2);
    cudaGetSymbolAddress((void**)&off1, g_off1);
    cudaGetSymbolAddress((void**)&off2, g_off2);
    cudaGetSymbolAddress((void**)&csr1, g_csr1);
    cudaGetSymbolAddress((void**)&csr2, g_csr2);
    cudaGetSymbolAddress((void**)&cs1,  g_csum1);
    cudaGetSymbolAddress((void**)&cs2,  g_csum2);

    static cudaStream_t s1 = nullptr, s2 = nullptr;
    static cudaEvent_t ev0 = nullptr, ev1 = nullptr, ev2 = nullptr;
    if (!s1) {
        cudaStreamCreateWithFlags(&s1, cudaStreamNonBlocking);
        cudaStreamCreateWithFlags(&s2, cudaStreamNonBlocking);
        cudaEventCreateWithFlags(&ev0, cudaEventDisableTiming);
        cudaEventCreateWithFlags(&ev1, cudaEventDisableTiming);
        cudaEventCreateWithFlags(&ev2, cudaEventDisableTiming);
        cudaFuncSetAttribute(k_gemm_mma<1>, cudaFuncAttributeMaxDynamicSharedMemorySize, GEMM_SMEM);
        cudaFuncSetAttribute(k_gemm_mma<2>, cudaFuncAttributeMaxDynamicSharedMemorySize, GEMM_SMEM);
    }

    const int ch1 = (N1 + 1023) / 1024;
    const int ch2 = (NS + 1023) / 1024;

    // fork side branches off the (captured) main stream
    cudaEventRecord(ev0, 0);
    cudaStreamWaitEvent(s1, ev0, 0);
    cudaStreamWaitEvent(s2, ev0, 0);

    // branch s1: graph-1 CSR + map init
    k_init1<<<(cNSOC + 255) / 256, 256, 0, s1>>>();
    k_hist<<<(E1 + 255) / 256, 256, 0, s1>>>(i2u_dst, cnt1, E1);
    k_scanA<<<ch1, 1024, 0, s1>>>(cnt1, off1, cs1, N1);
    k_scanB<<<1, 128, 0, s1>>>(cs1, ch1);
    k_scanC<<<(N1 + 255) / 256, 256, 0, s1>>>(off1, cs1, cnt1, N1);
    k_scatter<<<(E1 + 255) / 256, 256, 0, s1>>>(i2u_src, i2u_dst, cnt1, csr1, E1);
    cudaEventRecord(ev1, s1);

    // branch s2: graph-2 CSR
    k_init2<<<(cNSOC + 255) / 256, 256, 0, s2>>>();
    k_hist<<<(E2 + 255) / 256, 256, 0, s2>>>(soc_dst, cnt2, E2);
    k_scanA<<<ch2, 1024, 0, s2>>>(cnt2, off2, cs2, NS);
    k_scanB<<<1, 128, 0, s2>>>(cs2, ch2);
    k_scanC<<<(NS + 255) / 256, 256, 0, s2>>>(off2, cs2, cnt2, NS);
    k_scatter<<<(E2 + 255) / 256, 256, 0, s2>>>(soc_src, soc_dst, cnt2, csr2, E2);
    cudaEventRecord(ev2, s2);

    // main stream: W split, then layer-1 GEMM
    k_wsplit<<<256, 256>>>(Ws1, Wd1, Ws2, Wd2);
    k_gemm_mma<1><<<(N1 + 127) / 128, 512, GEMM_SMEM>>>(emb, i2u_nid, bs1, bd1, N1);

    // join graph-1 CSR, aggregate layer 1
    cudaStreamWaitEvent(0, ev1, 0);
    k_node<1><<<(N1 + 7) / 8, 256>>>(at1, nullptr, i2u_nid, N1);

    // layer-2 GEMM (needs h1 + map)
    k_gemm_mma<2><<<(NS + 127) / 128, 512, GEMM_SMEM>>>(emb, nullptr, bs2, bd2, NS);

    // join graph-2 CSR, aggregate layer 2 into d_out
    cudaStreamWaitEvent(0, ev2, 0);
    k_node<2><<<(NS + 7) / 8, 256>>>(at2, out, nullptr, NS);
}